// round 12
// baseline (speedup 1.0000x reference)
#include <cuda_runtime.h>
#include <cuda_fp16.h>
#include <mma.h>
#include <cstdint>

using namespace nvcuda;

#define TB      131072
#define TSTEPS  256
#define BATCH   512

// ---------------- device scratch ----------------
__device__ __align__(16) __half g_imgH[TB * 32];
__device__ __align__(16) __half g_f1H [TB * 256];
__device__ __align__(16) __half g_f2H [TB * 256];
__device__ __align__(16) __half g_f3H [TB * 128];
__device__ __align__(16) __half g_hidH[TB * 32];
__device__ __align__(16) __half g_xgH [TB * 512];     // fp16, gate-permuted cols (u*4+g)
__device__ __align__(16) __half g_W1H [256 * 32];
__device__ __align__(16) __half g_W2H [256 * 256];
__device__ __align__(16) __half g_W3H [128 * 256];
__device__ __align__(16) __half g_W4H [16 * 128];
__device__ __align__(16) __half g_WihH[512 * 32];     // gate-permuted rows
__device__ __align__(16) float  g_bg  [512];          // gate-permuted
__device__ __align__(16) __half g_whh [512 * 136];    // gate-permuted rows, padded ld=136

// ---------------- cp.async helpers ----------------
__device__ __forceinline__ void cp16(void* dst_smem, const void* src) {
    uint32_t d = (uint32_t)__cvta_generic_to_shared(dst_smem);
    asm volatile("cp.async.cg.shared.global [%0], [%1], 16;" :: "r"(d), "l"(src));
}
#define CP_COMMIT() asm volatile("cp.async.commit_group;" ::: "memory")
#define CP_WAIT(n)  asm volatile("cp.async.wait_group %0;" :: "n"(n) : "memory")

// ---------------- WMMA fp16 GEMM, cp.async double-buffered ----------------
// C[M,N] = op(A[M,K] @ W[N,K]^T + bias). Tile 128x128, BK=64, 8 warps x (32x64).
template<bool RELU, bool OUTF32>
__global__ void __launch_bounds__(256)
gemm_wmma(const __half* __restrict__ A, const __half* __restrict__ Bw,
          const float* __restrict__ bias, void* __restrict__ Cout,
          int K, int Nvalid, int ldc)
{
    extern __shared__ __align__(16) unsigned char sm[];
    // two stages of (A 128x72 + B 128x72) halves = 36864 B each; s_c overlays both
    float* s_c = (float*)sm;                 // 128 x 132 floats = 67584 B (<= 73728)

    const int tid = threadIdx.x, w = tid >> 5;
    const int m0 = blockIdx.x * 128, n0 = blockIdx.y * 128;
    const int wm = (w & 3) * 32;
    const int wn = (w >> 2) * 64;
    const int ntiles = (K + 63) >> 6;

    wmma::fragment<wmma::accumulator, 16, 16, 16, float> acc[2][4];
    #pragma unroll
    for (int i = 0; i < 2; i++)
        #pragma unroll
        for (int j = 0; j < 4; j++) wmma::fill_fragment(acc[i][j], 0.f);

    auto load_tile = [&](int kt, int stage) {
        int k0 = kt * 64;
        int kw = K - k0; if (kw > 64) kw = 64;
        int cpr = kw >> 3;
        __half* sa = (__half*)(sm + stage * 36864);
        __half* sb = sa + 128 * 72;
        for (int i = tid; i < 128 * cpr; i += 256) {
            int r = i / cpr, c = (i - r * cpr) << 3;
            cp16(sa + r * 72 + c, A + (size_t)(m0 + r) * K + k0 + c);
        }
        for (int i = tid; i < 128 * cpr; i += 256) {
            int r = i / cpr, c = (i - r * cpr) << 3;
            int rr = n0 + r; if (rr >= Nvalid) rr = Nvalid - 1;   // clamp; garbage cols never stored
            cp16(sb + r * 72 + c, Bw + (size_t)rr * K + k0 + c);
        }
        CP_COMMIT();
    };

    load_tile(0, 0);
    for (int kt = 0; kt < ntiles; kt++) {
        if (kt + 1 < ntiles) { load_tile(kt + 1, (kt + 1) & 1); CP_WAIT(1); }
        else                 { CP_WAIT(0); }
        __syncthreads();

        __half* sa = (__half*)(sm + (kt & 1) * 36864);
        __half* sb = sa + 128 * 72;
        int kw = K - kt * 64; if (kw > 64) kw = 64;
        const int steps = kw >> 4;
        for (int s = 0; s < steps; s++) {
            const int kk = s * 16;
            wmma::fragment<wmma::matrix_a, 16, 16, 16, half, wmma::row_major> af[2];
            wmma::fragment<wmma::matrix_b, 16, 16, 16, half, wmma::col_major> bf[4];
            #pragma unroll
            for (int i = 0; i < 2; i++)
                wmma::load_matrix_sync(af[i], sa + (wm + i * 16) * 72 + kk, 72);
            #pragma unroll
            for (int j = 0; j < 4; j++)
                wmma::load_matrix_sync(bf[j], sb + (wn + j * 16) * 72 + kk, 72);
            #pragma unroll
            for (int i = 0; i < 2; i++)
                #pragma unroll
                for (int j = 0; j < 4; j++)
                    wmma::mma_sync(acc[i][j], af[i], bf[j], acc[i][j]);
        }
        __syncthreads();
    }

    #pragma unroll
    for (int i = 0; i < 2; i++)
        #pragma unroll
        for (int j = 0; j < 4; j++)
            wmma::store_matrix_sync(s_c + (wm + i * 16) * 132 + wn + j * 16,
                                    acc[i][j], 132, wmma::mem_row_major);
    __syncthreads();

    const int r  = tid >> 1;
    const int ch = (tid & 1) << 6;
    const int row = m0 + r;
    int ncols = Nvalid - n0; if (ncols > 128) ncols = 128;

    if (OUTF32) {
        float* cp = (float*)Cout + (size_t)row * ldc + n0;
        #pragma unroll
        for (int q = 0; q < 16; q++) {
            int c0 = ch + q * 4;
            if (c0 >= ncols) break;
            float4 v;
            v.x = s_c[r * 132 + c0 + 0] + __ldg(bias + n0 + c0 + 0);
            v.y = s_c[r * 132 + c0 + 1] + __ldg(bias + n0 + c0 + 1);
            v.z = s_c[r * 132 + c0 + 2] + __ldg(bias + n0 + c0 + 2);
            v.w = s_c[r * 132 + c0 + 3] + __ldg(bias + n0 + c0 + 3);
            if (RELU) {
                v.x = fmaxf(v.x, 0.f); v.y = fmaxf(v.y, 0.f);
                v.z = fmaxf(v.z, 0.f); v.w = fmaxf(v.w, 0.f);
            }
            *(float4*)(cp + c0) = v;
        }
    } else {
        __half* cp = (__half*)Cout + (size_t)row * ldc + n0;
        #pragma unroll
        for (int q = 0; q < 8; q++) {
            int c0 = ch + q * 8;
            if (c0 >= ncols) break;
            __half2 hh[4];
            #pragma unroll
            for (int e = 0; e < 4; e++) {
                float x0 = s_c[r * 132 + c0 + 2 * e]     + __ldg(bias + n0 + c0 + 2 * e);
                float x1 = s_c[r * 132 + c0 + 2 * e + 1] + __ldg(bias + n0 + c0 + 2 * e + 1);
                if (RELU) { x0 = fmaxf(x0, 0.f); x1 = fmaxf(x1, 0.f); }
                hh[e] = __floats2half2_rn(x0, x1);
            }
            *(uint4*)(cp + c0) = *(uint4*)hh;
        }
    }
}

// ---------------- prep kernels (gate permutation: new row u*4+g <- old row g*128+u) ----------------
__global__ void prep_weights(const float* __restrict__ Wv1, const float* __restrict__ Wv2,
                             const float* __restrict__ Wv3, const float* __restrict__ Wv4,
                             const float* __restrict__ Wih, const float* __restrict__ bih,
                             const float* __restrict__ bhh, const float* __restrict__ Whh)
{
    int i = blockIdx.x * blockDim.x + threadIdx.x;
    if (i < 65536) {
        int nr = i >> 7, k = i & 127;
        int u = nr >> 2, g = nr & 3;
        g_whh[nr * 136 + k] = __float2half(Whh[((g << 7) + u) * 128 + k]);
        g_W2H[i] = __float2half(Wv2[i]);
    }
    if (i < 32768) g_W3H[i] = __float2half(Wv3[i]);
    if (i < 2048)  g_W4H[i] = __float2half(Wv4[i]);
    if (i < 8192) {
        int r = i >> 5, c = i & 31;
        g_W1H[i] = (c < 25) ? __float2half(Wv1[r * 25 + c]) : __half(0.f);
    }
    if (i < 16384) {
        int nr = i >> 5, c = i & 31;
        int u = nr >> 2, g = nr & 3;
        g_WihH[i] = (c < 24) ? __float2half(Wih[((g << 7) + u) * 24 + c]) : __half(0.f);
    }
    if (i < 512) {
        int u = i >> 2, g = i & 3;
        int orow = (g << 7) + u;
        g_bg[i] = bih[orow] + bhh[orow];
    }
}

__global__ void prep_img(const float* __restrict__ image)
{
    int i = blockIdx.x * blockDim.x + threadIdx.x;
    int r = i >> 5, c = i & 31;
    g_imgH[i] = (c < 25) ? __float2half(image[r * 25 + c] * (1.0f / 255.0f)) : __half(0.f);
}

__global__ void locmsg_h(const float* __restrict__ loc, const float* __restrict__ msg,
                         const int* __restrict__ done,
                         const float* __restrict__ Wl, const float* __restrict__ bl,
                         const float* __restrict__ Wm, const float* __restrict__ bm)
{
    int i = blockIdx.x * blockDim.x + threadIdx.x;
    if (i >= TB) return;
    float lx = loc[2 * i] * 0.1f, ly = loc[2 * i + 1] * 0.1f;
    float m = (1.f - (float)done[i]) * msg[i];
    __half h[16];
    #pragma unroll
    for (int c = 0; c < 4; c++) h[c] = __float2half(Wl[2*c] * lx + Wl[2*c+1] * ly + bl[c]);
    #pragma unroll
    for (int c = 0; c < 4; c++) h[4 + c] = __float2half(fmaxf(Wm[c] * m + bm[c], 0.f));
    #pragma unroll
    for (int c = 8; c < 16; c++) h[c] = __half(0.f);
    uint4* dst = (uint4*)(g_hidH + (size_t)i * 32 + 16);
    dst[0] = *(uint4*)&h[0];
    dst[1] = *(uint4*)&h[8];
}

// ---------------- tensor-core LSTM: gate-permuted, 1 barrier/step ----------------
__device__ __forceinline__ float sigf(float x)  { return 1.f / (1.f + __expf(-x)); }
__device__ __forceinline__ float tanhff(float x){ return 2.f / (1.f + __expf(-2.f * x)) - 1.f; }

#define LSTM_LB 8
// smem layout
#define LS_W   0
#define LS_H0  139264
#define LS_H1  141440
#define LS_G   143616
#define LS_TOT 160000

__global__ void __launch_bounds__(256, 1)
lstm_wmma(const int*   __restrict__ done,
          const float* __restrict__ h0,
          const float* __restrict__ c0,
          float* __restrict__ out_nh,
          float* __restrict__ out_h,
          float* __restrict__ out_c)
{
    extern __shared__ __align__(16) unsigned char sraw[];
    __half* s_w  = (__half*)(sraw + LS_W);       // 512 x 136 fp16 (gate-permuted rows)
    __half* s_hb[2] = { (__half*)(sraw + LS_H0), (__half*)(sraw + LS_H1) };  // 8 x 136 each
    float*  s_g  = (float*)(sraw + LS_G);        // per-warp 8x64 f32

    const int tid  = threadIdx.x;
    const int w    = tid >> 5, lane = tid & 31;
    const int ul   = lane & 15;                  // unit-local within warp's 16
    const int bh   = lane >> 4;                  // batch-half
    const int ug   = w * 16 + ul;                // global unit
    const int b0   = blockIdx.x * LSTM_LB;

    // stage Whh
    for (int i = tid; i < 512 * 136 * 2 / 16; i += 256)
        ((uint4*)s_w)[i] = ((const uint4*)g_whh)[i];
    // h0 masked -> fp16 buffer 0
    for (int i = tid; i < LSTM_LB * 128; i += 256) {
        int b = i >> 7, uu = i & 127;
        float m = 1.f - (float)done[b0 + b];
        s_hb[0][b * 136 + uu] = __float2half(h0[(b0 + b) * 128 + uu] * m);
    }
    float c[4];
    #pragma unroll
    for (int j = 0; j < 4; j++) {
        int b = bh * 4 + j;
        float m = 1.f - (float)done[b0 + b];
        c[j] = c0[(b0 + b) * 128 + ug] * m;
    }
    __syncthreads();

    // persistent Whh fragments: cols n0..n0+63 = all 4 gates of units [16w,16w+16)
    const int n0 = w * 64;
    wmma::fragment<wmma::matrix_b, 8, 32, 16, half, wmma::col_major> bf[16];
    #pragma unroll
    for (int k = 0; k < 8; k++)
        #pragma unroll
        for (int j = 0; j < 2; j++)
            wmma::load_matrix_sync(bf[k * 2 + j], s_w + (n0 + j * 32) * 136 + k * 16, 136);

    wmma::fragment<wmma::accumulator, 8, 32, 16, float> acc0, acc1;
    wmma::fragment<wmma::matrix_a, 8, 32, 16, half, wmma::row_major> af;
    float* gw = s_g + w * 512;                   // warp-private 8x64

    for (int t = 0; t < TSTEPS; t++) {
        const int cur = t & 1, nxt = cur ^ 1;

        // prefetch x-gates for THIS step (4 fp16 gates = 8B per cell) + next done masks
        uint2 xr[4];
        float dm[4];
        #pragma unroll
        for (int j = 0; j < 4; j++) {
            int b = bh * 4 + j;
            xr[j] = *(const uint2*)(g_xgH + ((size_t)t * BATCH + b0 + b) * 512 + ug * 4);
            if (t < TSTEPS - 1)
                dm[j] = 1.f - (float)done[(t + 1) * BATCH + b0 + b];
        }

        wmma::fill_fragment(acc0, 0.f);
        wmma::fill_fragment(acc1, 0.f);
        #pragma unroll
        for (int k = 0; k < 8; k++) {
            wmma::load_matrix_sync(af, s_hb[cur] + k * 16, 136);
            wmma::mma_sync(acc0, af, bf[k * 2 + 0], acc0);
            wmma::mma_sync(acc1, af, bf[k * 2 + 1], acc1);
        }
        wmma::store_matrix_sync(gw,      acc0, 64, wmma::mem_row_major);
        wmma::store_matrix_sync(gw + 32, acc1, 64, wmma::mem_row_major);
        __syncwarp();

        #pragma unroll
        for (int j = 0; j < 4; j++) {
            int b = bh * 4 + j;
            const float* gp = gw + b * 64 + ul * 4;
            __half2 x01 = *(__half2*)&xr[j].x;
            __half2 x23 = *(__half2*)&xr[j].y;
            float2 xa = __half22float2(x01), xb = __half22float2(x23);
            float ig = sigf  (gp[0] + xa.x);
            float fg = sigf  (gp[1] + xa.y);
            float gg = tanhff(gp[2] + xb.x);
            float og = sigf  (gp[3] + xb.y);
            float cn = fg * c[j] + ig * gg;
            float hn = og * tanhff(cn);
            out_nh[((size_t)t * BATCH + b0 + b) * 128 + ug] = hn;
            if (t < TSTEPS - 1) {
                c[j] = cn * dm[j];
                s_hb[nxt][b * 136 + ug] = __float2half(hn * dm[j]);
            } else {
                out_h[(b0 + b) * 128 + ug] = hn;
                out_c[(b0 + b) * 128 + ug] = cn;
            }
        }
        __syncthreads();
    }
}

// ---------------- launcher ----------------
extern "C" void kernel_launch(void* const* d_in, const int* in_sizes, int n_in,
                              void* d_out, int out_size)
{
    const float* image    = (const float*)d_in[0];
    const float* location = (const float*)d_in[1];
    const float* message  = (const float*)d_in[2];
    const int*   done     = (const int*)  d_in[3];
    const float* h0       = (const float*)d_in[4];
    const float* c0       = (const float*)d_in[5];
    const float* Wv1      = (const float*)d_in[6];
    const float* bv1      = (const float*)d_in[7];
    const float* Wv2      = (const float*)d_in[8];
    const float* bv2      = (const float*)d_in[9];
    const float* Wv3      = (const float*)d_in[10];
    const float* bv3      = (const float*)d_in[11];
    const float* Wv4      = (const float*)d_in[12];
    const float* bv4      = (const float*)d_in[13];
    const float* Wl       = (const float*)d_in[14];
    const float* bl       = (const float*)d_in[15];
    const float* Wm       = (const float*)d_in[16];
    const float* bm       = (const float*)d_in[17];
    const float* Wih      = (const float*)d_in[18];
    const float* bih      = (const float*)d_in[19];
    const float* Whh      = (const float*)d_in[20];
    const float* bhh      = (const float*)d_in[21];

    float* out_nh = (float*)d_out;
    float* out_h  = out_nh + (size_t)TB * 128;
    float* out_c  = out_h + (size_t)BATCH * 128;

    void *imgH, *f1H, *f2H, *f3H, *hidH, *xgH, *W1H, *W2H, *W3H, *W4H, *WihH, *bg;
    cudaGetSymbolAddress(&imgH, g_imgH);
    cudaGetSymbolAddress(&f1H,  g_f1H);
    cudaGetSymbolAddress(&f2H,  g_f2H);
    cudaGetSymbolAddress(&f3H,  g_f3H);
    cudaGetSymbolAddress(&hidH, g_hidH);
    cudaGetSymbolAddress(&xgH,  g_xgH);
    cudaGetSymbolAddress(&W1H,  g_W1H);
    cudaGetSymbolAddress(&W2H,  g_W2H);
    cudaGetSymbolAddress(&W3H,  g_W3H);
    cudaGetSymbolAddress(&W4H,  g_W4H);
    cudaGetSymbolAddress(&WihH, g_WihH);
    cudaGetSymbolAddress(&bg,   g_bg);

    const int gsm = 2 * 36864;               // 73728 B (s_c overlays)
    cudaFuncSetAttribute(gemm_wmma<true,  false>, cudaFuncAttributeMaxDynamicSharedMemorySize, gsm);
    cudaFuncSetAttribute(gemm_wmma<false, false>, cudaFuncAttributeMaxDynamicSharedMemorySize, gsm);
    cudaFuncSetAttribute(lstm_wmma, cudaFuncAttributeMaxDynamicSharedMemorySize, LS_TOT);

    prep_weights<<<256, 256>>>(Wv1, Wv2, Wv3, Wv4, Wih, bih, bhh, Whh);
    prep_img<<<TB * 32 / 256, 256>>>(image);

    gemm_wmma<true,  false><<<dim3(1024, 2), 256, gsm>>>((const __half*)imgH, (const __half*)W1H, bv1, f1H,  32, 256, 256);
    gemm_wmma<true,  false><<<dim3(1024, 2), 256, gsm>>>((const __half*)f1H,  (const __half*)W2H, bv2, f2H, 256, 256, 256);
    gemm_wmma<true,  false><<<dim3(1024, 1), 256, gsm>>>((const __half*)f2H,  (const __half*)W3H, bv3, f3H, 256, 128, 128);
    gemm_wmma<true,  false><<<dim3(1024, 1), 256, gsm>>>((const __half*)f3H,  (const __half*)W4H, bv4, hidH, 128, 16, 32);
    locmsg_h<<<(TB + 255) / 256, 256>>>(location, message, done, Wl, bl, Wm, bm);
    gemm_wmma<false, false><<<dim3(1024, 4), 256, gsm>>>((const __half*)hidH, (const __half*)WihH, (const float*)bg, xgH, 32, 512, 512);

    lstm_wmma<<<BATCH / LSTM_LB, 256, LS_TOT>>>(done, h0, c0, out_nh, out_h, out_c);
}

// round 13
// speedup vs baseline: 1.0464x; 1.0464x over previous
#include <cuda_runtime.h>
#include <cuda_fp16.h>
#include <mma.h>
#include <cstdint>

using namespace nvcuda;

#define TB      131072
#define TSTEPS  256
#define BATCH   512

// ---------------- device scratch ----------------
__device__ __align__(16) __half g_imgH[TB * 32];
__device__ __align__(16) __half g_f1H [TB * 256];
__device__ __align__(16) __half g_f2H [TB * 256];
__device__ __align__(16) __half g_f3H [TB * 128];
__device__ __align__(16) __half g_hidH[TB * 32];
__device__ __align__(16) float  g_xg  [TB * 512];     // fp32, standard gate-major layout
__device__ __align__(16) __half g_W1H [256 * 32];
__device__ __align__(16) __half g_W2H [256 * 256];
__device__ __align__(16) __half g_W3H [128 * 256];
__device__ __align__(16) __half g_W4H [16 * 128];
__device__ __align__(16) __half g_WihH[512 * 32];
__device__ __align__(16) float  g_bg  [512];
__device__ __align__(16) __half g_whh [512 * 136];    // unpermuted rows, padded ld=136

// ---------------- cp.async helpers ----------------
__device__ __forceinline__ void cp16(void* dst_smem, const void* src) {
    uint32_t d = (uint32_t)__cvta_generic_to_shared(dst_smem);
    asm volatile("cp.async.cg.shared.global [%0], [%1], 16;" :: "r"(d), "l"(src));
}
#define CP_COMMIT() asm volatile("cp.async.commit_group;" ::: "memory")
#define CP_WAIT(n)  asm volatile("cp.async.wait_group %0;" :: "n"(n) : "memory")

// ---------------- WMMA fp16 GEMM, cp.async double-buffered, 2 CTA/SM ----------------
template<bool RELU, bool OUTF32>
__global__ void __launch_bounds__(256, 2)
gemm_wmma(const __half* __restrict__ A, const __half* __restrict__ Bw,
          const float* __restrict__ bias, void* __restrict__ Cout,
          int K, int Nvalid, int ldc)
{
    extern __shared__ __align__(16) unsigned char sm[];
    float* s_c = (float*)sm;                 // reuse both stages: 128x132 f32 = 67584 B

    const int tid = threadIdx.x, w = tid >> 5;
    const int m0 = blockIdx.x * 128, n0 = blockIdx.y * 128;
    const int wm = (w & 3) * 32;
    const int wn = (w >> 2) * 64;
    const int ntiles = (K + 63) >> 6;

    wmma::fragment<wmma::accumulator, 16, 16, 16, float> acc[2][4];
    #pragma unroll
    for (int i = 0; i < 2; i++)
        #pragma unroll
        for (int j = 0; j < 4; j++) wmma::fill_fragment(acc[i][j], 0.f);

    auto load_tile = [&](int kt, int stage) {
        int k0 = kt * 64;
        int kw = K - k0; if (kw > 64) kw = 64;
        int cpr = kw >> 3;
        __half* sa = (__half*)(sm + stage * 36864);
        __half* sb = sa + 128 * 72;
        for (int i = tid; i < 128 * cpr; i += 256) {
            int r = i / cpr, c = (i - r * cpr) << 3;
            cp16(sa + r * 72 + c, A + (size_t)(m0 + r) * K + k0 + c);
        }
        for (int i = tid; i < 128 * cpr; i += 256) {
            int r = i / cpr, c = (i - r * cpr) << 3;
            int rr = n0 + r; if (rr >= Nvalid) rr = Nvalid - 1;   // clamp; extra cols never stored
            cp16(sb + r * 72 + c, Bw + (size_t)rr * K + k0 + c);
        }
        CP_COMMIT();
    };

    load_tile(0, 0);
    for (int kt = 0; kt < ntiles; kt++) {
        if (kt + 1 < ntiles) { load_tile(kt + 1, (kt + 1) & 1); CP_WAIT(1); }
        else                 { CP_WAIT(0); }
        __syncthreads();

        __half* sa = (__half*)(sm + (kt & 1) * 36864);
        __half* sb = sa + 128 * 72;
        int kw = K - kt * 64; if (kw > 64) kw = 64;
        const int steps = kw >> 4;
        for (int s = 0; s < steps; s++) {
            const int kk = s * 16;
            wmma::fragment<wmma::matrix_a, 16, 16, 16, half, wmma::row_major> af[2];
            wmma::fragment<wmma::matrix_b, 16, 16, 16, half, wmma::col_major> bf[4];
            #pragma unroll
            for (int i = 0; i < 2; i++)
                wmma::load_matrix_sync(af[i], sa + (wm + i * 16) * 72 + kk, 72);
            #pragma unroll
            for (int j = 0; j < 4; j++)
                wmma::load_matrix_sync(bf[j], sb + (wn + j * 16) * 72 + kk, 72);
            #pragma unroll
            for (int i = 0; i < 2; i++)
                #pragma unroll
                for (int j = 0; j < 4; j++)
                    wmma::mma_sync(acc[i][j], af[i], bf[j], acc[i][j]);
        }
        __syncthreads();
    }

    #pragma unroll
    for (int i = 0; i < 2; i++)
        #pragma unroll
        for (int j = 0; j < 4; j++)
            wmma::store_matrix_sync(s_c + (wm + i * 16) * 132 + wn + j * 16,
                                    acc[i][j], 132, wmma::mem_row_major);
    __syncthreads();

    const int r  = tid >> 1;
    const int ch = (tid & 1) << 6;
    const int row = m0 + r;
    int ncols = Nvalid - n0; if (ncols > 128) ncols = 128;

    if (OUTF32) {
        float* cp = (float*)Cout + (size_t)row * ldc + n0;
        #pragma unroll
        for (int q = 0; q < 16; q++) {
            int c0 = ch + q * 4;
            if (c0 >= ncols) break;
            float4 v;
            v.x = s_c[r * 132 + c0 + 0] + __ldg(bias + n0 + c0 + 0);
            v.y = s_c[r * 132 + c0 + 1] + __ldg(bias + n0 + c0 + 1);
            v.z = s_c[r * 132 + c0 + 2] + __ldg(bias + n0 + c0 + 2);
            v.w = s_c[r * 132 + c0 + 3] + __ldg(bias + n0 + c0 + 3);
            if (RELU) {
                v.x = fmaxf(v.x, 0.f); v.y = fmaxf(v.y, 0.f);
                v.z = fmaxf(v.z, 0.f); v.w = fmaxf(v.w, 0.f);
            }
            *(float4*)(cp + c0) = v;
        }
    } else {
        __half* cp = (__half*)Cout + (size_t)row * ldc + n0;
        #pragma unroll
        for (int q = 0; q < 8; q++) {
            int c0 = ch + q * 8;
            if (c0 >= ncols) break;
            __half2 hh[4];
            #pragma unroll
            for (int e = 0; e < 4; e++) {
                float x0 = s_c[r * 132 + c0 + 2 * e]     + __ldg(bias + n0 + c0 + 2 * e);
                float x1 = s_c[r * 132 + c0 + 2 * e + 1] + __ldg(bias + n0 + c0 + 2 * e + 1);
                if (RELU) { x0 = fmaxf(x0, 0.f); x1 = fmaxf(x1, 0.f); }
                hh[e] = __floats2half2_rn(x0, x1);
            }
            *(uint4*)(cp + c0) = *(uint4*)hh;
        }
    }
}

// ---------------- prep kernels (unpermuted, R11 layout) ----------------
__global__ void prep_weights(const float* __restrict__ Wv1, const float* __restrict__ Wv2,
                             const float* __restrict__ Wv3, const float* __restrict__ Wv4,
                             const float* __restrict__ Wih, const float* __restrict__ bih,
                             const float* __restrict__ bhh, const float* __restrict__ Whh)
{
    int i = blockIdx.x * blockDim.x + threadIdx.x;
    if (i < 65536) {
        g_whh[(i >> 7) * 136 + (i & 127)] = __float2half(Whh[i]);
        g_W2H[i] = __float2half(Wv2[i]);
    }
    if (i < 32768) g_W3H[i] = __float2half(Wv3[i]);
    if (i < 2048)  g_W4H[i] = __float2half(Wv4[i]);
    if (i < 8192) {
        int r = i >> 5, c = i & 31;
        g_W1H[i] = (c < 25) ? __float2half(Wv1[r * 25 + c]) : __half(0.f);
    }
    if (i < 16384) {
        int r = i >> 5, c = i & 31;
        g_WihH[i] = (c < 24) ? __float2half(Wih[r * 24 + c]) : __half(0.f);
    }
    if (i < 512) g_bg[i] = bih[i] + bhh[i];
}

__global__ void prep_img(const float* __restrict__ image)
{
    int i = blockIdx.x * blockDim.x + threadIdx.x;
    int r = i >> 5, c = i & 31;
    g_imgH[i] = (c < 25) ? __float2half(image[r * 25 + c] * (1.0f / 255.0f)) : __half(0.f);
}

__global__ void locmsg_h(const float* __restrict__ loc, const float* __restrict__ msg,
                         const int* __restrict__ done,
                         const float* __restrict__ Wl, const float* __restrict__ bl,
                         const float* __restrict__ Wm, const float* __restrict__ bm)
{
    int i = blockIdx.x * blockDim.x + threadIdx.x;
    if (i >= TB) return;
    float lx = loc[2 * i] * 0.1f, ly = loc[2 * i + 1] * 0.1f;
    float m = (1.f - (float)done[i]) * msg[i];
    __half h[16];
    #pragma unroll
    for (int c = 0; c < 4; c++) h[c] = __float2half(Wl[2*c] * lx + Wl[2*c+1] * ly + bl[c]);
    #pragma unroll
    for (int c = 0; c < 4; c++) h[4 + c] = __float2half(fmaxf(Wm[c] * m + bm[c], 0.f));
    #pragma unroll
    for (int c = 8; c < 16; c++) h[c] = __half(0.f);
    uint4* dst = (uint4*)(g_hidH + (size_t)i * 32 + 16);
    dst[0] = *(uint4*)&h[0];
    dst[1] = *(uint4*)&h[8];
}

// ---------------- tensor-core LSTM (R11 structure, cp.async x staging, fast tanh) ----------------
__device__ __forceinline__ float sigf(float x)  { return 1.f / (1.f + __expf(-x)); }
__device__ __forceinline__ float tanhff(float x){ return 2.f / (1.f + __expf(-2.f * x)) - 1.f; }

#define LSTM_LB 8

__global__ void __launch_bounds__(256, 1)
lstm_wmma(const int*   __restrict__ done,
          const float* __restrict__ h0,
          const float* __restrict__ c0,
          float* __restrict__ out_nh,
          float* __restrict__ out_h,
          float* __restrict__ out_c)
{
    extern __shared__ __align__(16) unsigned char sraw[];
    __half* s_w     = (__half*)sraw;                              // 512*136 h = 139264 B
    __half* s_h     = (__half*)(sraw + 139264);                   // 8*136 h  = 2176 B
    float*  s_gates = (float*)(sraw + 139264 + 2176);             // 8*516 f  = 16512 B
    float*  s_x     = (float*)(sraw + 139264 + 2176 + 16512);     // 8*512 f  = 16384 B

    const int tid = threadIdx.x, w = tid >> 5;
    const int b0  = blockIdx.x * LSTM_LB;
    const int u   = tid & 127;
    const int bg  = (tid >> 7) * 4;      // this thread's 4 batch rows
    const int n0  = w * 64;

    for (int i = tid; i < 512 * 136 * 2 / 16; i += 256)
        ((uint4*)s_w)[i] = ((const uint4*)g_whh)[i];
    for (int i = tid; i < LSTM_LB * 128; i += 256) {
        int b = i >> 7, uu = i & 127;
        float m = 1.f - (float)done[b0 + b];
        s_h[b * 136 + uu] = __float2half(h0[(b0 + b) * 128 + uu] * m);
    }
    // stage xg(t=0) via cp.async
    {
        const float* src = g_xg + (size_t)b0 * 512;
        #pragma unroll
        for (int i = 0; i < 4; i++)
            cp16(s_x + (tid + 256 * i) * 4, src + (tid + 256 * i) * 4);
        CP_COMMIT();
    }
    float c[4];
    #pragma unroll
    for (int j = 0; j < 4; j++) {
        int b = bg + j;
        float m = 1.f - (float)done[b0 + b];
        c[j] = c0[(b0 + b) * 128 + u] * m;
    }
    CP_WAIT(0);
    __syncthreads();

    // persistent Whh fragments
    wmma::fragment<wmma::matrix_b, 8, 32, 16, half, wmma::col_major> bf[16];
    #pragma unroll
    for (int k = 0; k < 8; k++)
        #pragma unroll
        for (int j = 0; j < 2; j++)
            wmma::load_matrix_sync(bf[k * 2 + j], s_w + (n0 + j * 32) * 136 + k * 16, 136);

    wmma::fragment<wmma::accumulator, 8, 32, 16, float> acc0, acc1;
    wmma::fragment<wmma::matrix_a, 8, 32, 16, half, wmma::row_major> af;

    for (int t = 0; t < TSTEPS; t++) {
        float dm[4];
        if (t < TSTEPS - 1) {
            #pragma unroll
            for (int j = 0; j < 4; j++)
                dm[j] = 1.f - (float)done[(t + 1) * BATCH + b0 + bg + j];
        }

        wmma::fill_fragment(acc0, 0.f);
        wmma::fill_fragment(acc1, 0.f);
        #pragma unroll
        for (int k = 0; k < 8; k++) {
            wmma::load_matrix_sync(af, s_h + k * 16, 136);
            wmma::mma_sync(acc0, af, bf[k * 2 + 0], acc0);
            wmma::mma_sync(acc1, af, bf[k * 2 + 1], acc1);
        }
        CP_WAIT(0);                               // xg(t) staging drained under mma
        wmma::store_matrix_sync(s_gates + n0,      acc0, 516, wmma::mem_row_major);
        wmma::store_matrix_sync(s_gates + n0 + 32, acc1, 516, wmma::mem_row_major);
        __syncthreads();

        #pragma unroll
        for (int j = 0; j < 4; j++) {
            int b = bg + j;
            const float* gp = s_gates + b * 516;
            const float* xp = s_x + b * 512;
            float ig = sigf  (gp[u]       + xp[u]);
            float fg = sigf  (gp[128 + u] + xp[128 + u]);
            float gg = tanhff(gp[256 + u] + xp[256 + u]);
            float og = sigf  (gp[384 + u] + xp[384 + u]);
            float cn = fg * c[j] + ig * gg;
            float hn = og * tanhff(cn);
            out_nh[((size_t)t * BATCH + b0 + b) * 128 + u] = hn;
            if (t < TSTEPS - 1) {
                c[j] = cn * dm[j];
                s_h[b * 136 + u] = __float2half(hn * dm[j]);
            } else {
                out_h[(b0 + b) * 128 + u] = hn;
                out_c[(b0 + b) * 128 + u] = cn;
            }
        }
        __syncthreads();

        if (t < TSTEPS - 1) {                     // issue xg(t+1) staging; drains under next mma
            const float* src = g_xg + ((size_t)(t + 1) * BATCH + b0) * 512;
            #pragma unroll
            for (int i = 0; i < 4; i++)
                cp16(s_x + (tid + 256 * i) * 4, src + (tid + 256 * i) * 4);
            CP_COMMIT();
        }
    }
}

// ---------------- launcher ----------------
extern "C" void kernel_launch(void* const* d_in, const int* in_sizes, int n_in,
                              void* d_out, int out_size)
{
    const float* image    = (const float*)d_in[0];
    const float* location = (const float*)d_in[1];
    const float* message  = (const float*)d_in[2];
    const int*   done     = (const int*)  d_in[3];
    const float* h0       = (const float*)d_in[4];
    const float* c0       = (const float*)d_in[5];
    const float* Wv1      = (const float*)d_in[6];
    const float* bv1      = (const float*)d_in[7];
    const float* Wv2      = (const float*)d_in[8];
    const float* bv2      = (const float*)d_in[9];
    const float* Wv3      = (const float*)d_in[10];
    const float* bv3      = (const float*)d_in[11];
    const float* Wv4      = (const float*)d_in[12];
    const float* bv4      = (const float*)d_in[13];
    const float* Wl       = (const float*)d_in[14];
    const float* bl       = (const float*)d_in[15];
    const float* Wm       = (const float*)d_in[16];
    const float* bm       = (const float*)d_in[17];
    const float* Wih      = (const float*)d_in[18];
    const float* bih      = (const float*)d_in[19];
    const float* Whh      = (const float*)d_in[20];
    const float* bhh      = (const float*)d_in[21];

    float* out_nh = (float*)d_out;
    float* out_h  = out_nh + (size_t)TB * 128;
    float* out_c  = out_h + (size_t)BATCH * 128;

    void *imgH, *f1H, *f2H, *f3H, *hidH, *xg, *W1H, *W2H, *W3H, *W4H, *WihH, *bg;
    cudaGetSymbolAddress(&imgH, g_imgH);
    cudaGetSymbolAddress(&f1H,  g_f1H);
    cudaGetSymbolAddress(&f2H,  g_f2H);
    cudaGetSymbolAddress(&f3H,  g_f3H);
    cudaGetSymbolAddress(&hidH, g_hidH);
    cudaGetSymbolAddress(&xg,   g_xg);
    cudaGetSymbolAddress(&W1H,  g_W1H);
    cudaGetSymbolAddress(&W2H,  g_W2H);
    cudaGetSymbolAddress(&W3H,  g_W3H);
    cudaGetSymbolAddress(&W4H,  g_W4H);
    cudaGetSymbolAddress(&WihH, g_WihH);
    cudaGetSymbolAddress(&bg,   g_bg);

    const int gsm = 2 * 36864;                       // 73728 B
    const int lsm = 139264 + 2176 + 16512 + 16384;   // 174336 B
    cudaFuncSetAttribute(gemm_wmma<true,  false>, cudaFuncAttributeMaxDynamicSharedMemorySize, gsm);
    cudaFuncSetAttribute(gemm_wmma<false, true >, cudaFuncAttributeMaxDynamicSharedMemorySize, gsm);
    cudaFuncSetAttribute(lstm_wmma, cudaFuncAttributeMaxDynamicSharedMemorySize, lsm);

    prep_weights<<<256, 256>>>(Wv1, Wv2, Wv3, Wv4, Wih, bih, bhh, Whh);
    prep_img<<<TB * 32 / 256, 256>>>(image);

    gemm_wmma<true,  false><<<dim3(1024, 2), 256, gsm>>>((const __half*)imgH, (const __half*)W1H, bv1, f1H,  32, 256, 256);
    gemm_wmma<true,  false><<<dim3(1024, 2), 256, gsm>>>((const __half*)f1H,  (const __half*)W2H, bv2, f2H, 256, 256, 256);
    gemm_wmma<true,  false><<<dim3(1024, 1), 256, gsm>>>((const __half*)f2H,  (const __half*)W3H, bv3, f3H, 256, 128, 128);
    gemm_wmma<true,  false><<<dim3(1024, 1), 256, gsm>>>((const __half*)f3H,  (const __half*)W4H, bv4, hidH, 128, 16, 32);
    locmsg_h<<<(TB + 255) / 256, 256>>>(location, message, done, Wl, bl, Wm, bm);
    gemm_wmma<false, true ><<<dim3(1024, 4), 256, gsm>>>((const __half*)hidH, (const __half*)WihH, (const float*)bg, xg, 32, 512, 512);

    lstm_wmma<<<BATCH / LSTM_LB, 256, lsm>>>(done, h0, c0, out_nh, out_h, out_c);
}

// round 14
// speedup vs baseline: 1.1186x; 1.0690x over previous
#include <cuda_runtime.h>
#include <cuda_fp16.h>
#include <mma.h>
#include <cstdint>

using namespace nvcuda;

#define TB      131072
#define TSTEPS  256
#define BATCH   512

// ---------------- device scratch ----------------
__device__ __align__(16) __half g_imgH[TB * 32];
__device__ __align__(16) __half g_f1H [TB * 256];
__device__ __align__(16) __half g_f2H [TB * 256];
__device__ __align__(16) __half g_f3H [TB * 128];
__device__ __align__(16) __half g_hidH[TB * 32];
__device__ __align__(16) __half g_xgH [TB * 512];     // fp16, standard gate-major layout
__device__ __align__(16) __half g_W1H [256 * 32];
__device__ __align__(16) __half g_W2H [256 * 256];
__device__ __align__(16) __half g_W3H [128 * 256];
__device__ __align__(16) __half g_W4H [16 * 128];
__device__ __align__(16) __half g_WihH[512 * 32];
__device__ __align__(16) float  g_bg  [512];
__device__ __align__(16) __half g_whh [512 * 136];    // unpermuted rows, padded ld=136

// ---------------- cp.async helpers ----------------
__device__ __forceinline__ void cp16(void* dst_smem, const void* src) {
    uint32_t d = (uint32_t)__cvta_generic_to_shared(dst_smem);
    asm volatile("cp.async.cg.shared.global [%0], [%1], 16;" :: "r"(d), "l"(src));
}
#define CP_COMMIT() asm volatile("cp.async.commit_group;" ::: "memory")
#define CP_WAIT(n)  asm volatile("cp.async.wait_group %0;" :: "n"(n) : "memory")

// ---------------- WMMA fp16 GEMM, cp.async double-buffered (measured R13) ----------------
template<bool RELU, bool OUTF32>
__global__ void __launch_bounds__(256, 2)
gemm_wmma(const __half* __restrict__ A, const __half* __restrict__ Bw,
          const float* __restrict__ bias, void* __restrict__ Cout,
          int K, int Nvalid, int ldc)
{
    extern __shared__ __align__(16) unsigned char sm[];
    float* s_c = (float*)sm;                 // reuse both stages: 128x132 f32

    const int tid = threadIdx.x, w = tid >> 5;
    const int m0 = blockIdx.x * 128, n0 = blockIdx.y * 128;
    const int wm = (w & 3) * 32;
    const int wn = (w >> 2) * 64;
    const int ntiles = (K + 63) >> 6;

    wmma::fragment<wmma::accumulator, 16, 16, 16, float> acc[2][4];
    #pragma unroll
    for (int i = 0; i < 2; i++)
        #pragma unroll
        for (int j = 0; j < 4; j++) wmma::fill_fragment(acc[i][j], 0.f);

    auto load_tile = [&](int kt, int stage) {
        int k0 = kt * 64;
        int kw = K - k0; if (kw > 64) kw = 64;
        int cpr = kw >> 3;
        __half* sa = (__half*)(sm + stage * 36864);
        __half* sb = sa + 128 * 72;
        for (int i = tid; i < 128 * cpr; i += 256) {
            int r = i / cpr, c = (i - r * cpr) << 3;
            cp16(sa + r * 72 + c, A + (size_t)(m0 + r) * K + k0 + c);
        }
        for (int i = tid; i < 128 * cpr; i += 256) {
            int r = i / cpr, c = (i - r * cpr) << 3;
            int rr = n0 + r; if (rr >= Nvalid) rr = Nvalid - 1;
            cp16(sb + r * 72 + c, Bw + (size_t)rr * K + k0 + c);
        }
        CP_COMMIT();
    };

    load_tile(0, 0);
    for (int kt = 0; kt < ntiles; kt++) {
        if (kt + 1 < ntiles) { load_tile(kt + 1, (kt + 1) & 1); CP_WAIT(1); }
        else                 { CP_WAIT(0); }
        __syncthreads();

        __half* sa = (__half*)(sm + (kt & 1) * 36864);
        __half* sb = sa + 128 * 72;
        int kw = K - kt * 64; if (kw > 64) kw = 64;
        const int steps = kw >> 4;
        for (int s = 0; s < steps; s++) {
            const int kk = s * 16;
            wmma::fragment<wmma::matrix_a, 16, 16, 16, half, wmma::row_major> af[2];
            wmma::fragment<wmma::matrix_b, 16, 16, 16, half, wmma::col_major> bf[4];
            #pragma unroll
            for (int i = 0; i < 2; i++)
                wmma::load_matrix_sync(af[i], sa + (wm + i * 16) * 72 + kk, 72);
            #pragma unroll
            for (int j = 0; j < 4; j++)
                wmma::load_matrix_sync(bf[j], sb + (wn + j * 16) * 72 + kk, 72);
            #pragma unroll
            for (int i = 0; i < 2; i++)
                #pragma unroll
                for (int j = 0; j < 4; j++)
                    wmma::mma_sync(acc[i][j], af[i], bf[j], acc[i][j]);
        }
        __syncthreads();
    }

    #pragma unroll
    for (int i = 0; i < 2; i++)
        #pragma unroll
        for (int j = 0; j < 4; j++)
            wmma::store_matrix_sync(s_c + (wm + i * 16) * 132 + wn + j * 16,
                                    acc[i][j], 132, wmma::mem_row_major);
    __syncthreads();

    const int r  = tid >> 1;
    const int ch = (tid & 1) << 6;
    const int row = m0 + r;
    int ncols = Nvalid - n0; if (ncols > 128) ncols = 128;

    if (OUTF32) {
        float* cp = (float*)Cout + (size_t)row * ldc + n0;
        #pragma unroll
        for (int q = 0; q < 16; q++) {
            int c0 = ch + q * 4;
            if (c0 >= ncols) break;
            float4 v;
            v.x = s_c[r * 132 + c0 + 0] + __ldg(bias + n0 + c0 + 0);
            v.y = s_c[r * 132 + c0 + 1] + __ldg(bias + n0 + c0 + 1);
            v.z = s_c[r * 132 + c0 + 2] + __ldg(bias + n0 + c0 + 2);
            v.w = s_c[r * 132 + c0 + 3] + __ldg(bias + n0 + c0 + 3);
            if (RELU) {
                v.x = fmaxf(v.x, 0.f); v.y = fmaxf(v.y, 0.f);
                v.z = fmaxf(v.z, 0.f); v.w = fmaxf(v.w, 0.f);
            }
            *(float4*)(cp + c0) = v;
        }
    } else {
        __half* cp = (__half*)Cout + (size_t)row * ldc + n0;
        #pragma unroll
        for (int q = 0; q < 8; q++) {
            int c0 = ch + q * 8;
            if (c0 >= ncols) break;
            __half2 hh[4];
            #pragma unroll
            for (int e = 0; e < 4; e++) {
                float x0 = s_c[r * 132 + c0 + 2 * e]     + __ldg(bias + n0 + c0 + 2 * e);
                float x1 = s_c[r * 132 + c0 + 2 * e + 1] + __ldg(bias + n0 + c0 + 2 * e + 1);
                if (RELU) { x0 = fmaxf(x0, 0.f); x1 = fmaxf(x1, 0.f); }
                hh[e] = __floats2half2_rn(x0, x1);
            }
            *(uint4*)(cp + c0) = *(uint4*)hh;
        }
    }
}

// ---------------- prep kernels ----------------
__global__ void prep_weights(const float* __restrict__ Wv1, const float* __restrict__ Wv2,
                             const float* __restrict__ Wv3, const float* __restrict__ Wv4,
                             const float* __restrict__ Wih, const float* __restrict__ bih,
                             const float* __restrict__ bhh, const float* __restrict__ Whh)
{
    int i = blockIdx.x * blockDim.x + threadIdx.x;
    if (i < 65536) {
        g_whh[(i >> 7) * 136 + (i & 127)] = __float2half(Whh[i]);
        g_W2H[i] = __float2half(Wv2[i]);
    }
    if (i < 32768) g_W3H[i] = __float2half(Wv3[i]);
    if (i < 2048)  g_W4H[i] = __float2half(Wv4[i]);
    if (i < 8192) {
        int r = i >> 5, c = i & 31;
        g_W1H[i] = (c < 25) ? __float2half(Wv1[r * 25 + c]) : __half(0.f);
    }
    if (i < 16384) {
        int r = i >> 5, c = i & 31;
        g_WihH[i] = (c < 24) ? __float2half(Wih[r * 24 + c]) : __half(0.f);
    }
    if (i < 512) g_bg[i] = bih[i] + bhh[i];
}

__global__ void prep_img(const float* __restrict__ image)
{
    int i = blockIdx.x * blockDim.x + threadIdx.x;
    int r = i >> 5, c = i & 31;
    g_imgH[i] = (c < 25) ? __float2half(image[r * 25 + c] * (1.0f / 255.0f)) : __half(0.f);
}

__global__ void locmsg_h(const float* __restrict__ loc, const float* __restrict__ msg,
                         const int* __restrict__ done,
                         const float* __restrict__ Wl, const float* __restrict__ bl,
                         const float* __restrict__ Wm, const float* __restrict__ bm)
{
    int i = blockIdx.x * blockDim.x + threadIdx.x;
    if (i >= TB) return;
    float lx = loc[2 * i] * 0.1f, ly = loc[2 * i + 1] * 0.1f;
    float m = (1.f - (float)done[i]) * msg[i];
    __half h[16];
    #pragma unroll
    for (int c = 0; c < 4; c++) h[c] = __float2half(Wl[2*c] * lx + Wl[2*c+1] * ly + bl[c]);
    #pragma unroll
    for (int c = 0; c < 4; c++) h[4 + c] = __float2half(fmaxf(Wm[c] * m + bm[c], 0.f));
    #pragma unroll
    for (int c = 8; c < 16; c++) h[c] = __half(0.f);
    uint4* dst = (uint4*)(g_hidH + (size_t)i * 32 + 16);
    dst[0] = *(uint4*)&h[0];
    dst[1] = *(uint4*)&h[8];
}

// ---------------- tensor-core LSTM: R11 structure verbatim, xg in fp16 ----------------
__device__ __forceinline__ float sigf(float x) { return 1.f / (1.f + __expf(-x)); }

#define LSTM_LB 8

__global__ void __launch_bounds__(256, 1)
lstm_wmma(const int*   __restrict__ done,
          const float* __restrict__ h0,
          const float* __restrict__ c0,
          float* __restrict__ out_nh,
          float* __restrict__ out_h,
          float* __restrict__ out_c)
{
    extern __shared__ __align__(16) unsigned char sraw[];
    __half* s_w     = (__half*)sraw;                              // 512*136 h = 139264 B
    __half* s_h     = (__half*)(sraw + 139264);                   // 8*136 h  = 2176 B
    float*  s_gates = (float*)(sraw + 139264 + 2176);             // 8*516 f  = 16512 B
    __half* s_x     = (__half*)(sraw + 139264 + 2176 + 16512);    // 8*512 h  = 8192 B

    const int tid = threadIdx.x, w = tid >> 5;
    const int b0  = blockIdx.x * LSTM_LB;
    const int u   = tid & 127;
    const int bg  = (tid >> 7) * 4;      // this thread's 4 batch rows
    const int n0  = w * 64;

    // stage Whh
    for (int i = tid; i < 512 * 136 * 2 / 16; i += 256)
        ((uint4*)s_w)[i] = ((const uint4*)g_whh)[i];
    // h0 masked -> fp16
    for (int i = tid; i < LSTM_LB * 128; i += 256) {
        int b = i >> 7, uu = i & 127;
        float m = 1.f - (float)done[b0 + b];
        s_h[b * 136 + uu] = __float2half(h0[(b0 + b) * 128 + uu] * m);
    }
    // stage xg(t=0): 8*512 halves = 512 uint4
    {
        const uint4* src = (const uint4*)(g_xgH + (size_t)b0 * 512);
        ((uint4*)s_x)[tid]       = src[tid];
        ((uint4*)s_x)[tid + 256] = src[tid + 256];
    }
    float c[4];
    #pragma unroll
    for (int j = 0; j < 4; j++) {
        int b = bg + j;
        float m = 1.f - (float)done[b0 + b];
        c[j] = c0[(b0 + b) * 128 + u] * m;
    }
    __syncthreads();

    // persistent Whh fragments
    wmma::fragment<wmma::matrix_b, 8, 32, 16, half, wmma::col_major> bf[16];
    #pragma unroll
    for (int k = 0; k < 8; k++)
        #pragma unroll
        for (int j = 0; j < 2; j++)
            wmma::load_matrix_sync(bf[k * 2 + j], s_w + (n0 + j * 32) * 136 + k * 16, 136);

    wmma::fragment<wmma::accumulator, 8, 32, 16, float> acc0, acc1;
    wmma::fragment<wmma::matrix_a, 8, 32, 16, half, wmma::row_major> af;

    for (int t = 0; t < TSTEPS; t++) {
        // prefetch next-step done masks (latency hidden under mma)
        float dm[4];
        if (t < TSTEPS - 1) {
            #pragma unroll
            for (int j = 0; j < 4; j++)
                dm[j] = 1.f - (float)done[(t + 1) * BATCH + b0 + bg + j];
        }

        wmma::fill_fragment(acc0, 0.f);
        wmma::fill_fragment(acc1, 0.f);
        #pragma unroll
        for (int k = 0; k < 8; k++) {
            wmma::load_matrix_sync(af, s_h + k * 16, 136);
            wmma::mma_sync(acc0, af, bf[k * 2 + 0], acc0);
            wmma::mma_sync(acc1, af, bf[k * 2 + 1], acc1);
        }
        wmma::store_matrix_sync(s_gates + n0,      acc0, 516, wmma::mem_row_major);
        wmma::store_matrix_sync(s_gates + n0 + 32, acc1, 516, wmma::mem_row_major);
        __syncthreads();

        // activation: 4 cells per thread
        #pragma unroll
        for (int j = 0; j < 4; j++) {
            int b = bg + j;
            const float*  gp = s_gates + b * 516;
            const __half* xp = s_x + b * 512;
            float ig = sigf (gp[u]       + __half2float(xp[u]));
            float fg = sigf (gp[128 + u] + __half2float(xp[128 + u]));
            float gg = tanhf(gp[256 + u] + __half2float(xp[256 + u]));
            float og = sigf (gp[384 + u] + __half2float(xp[384 + u]));
            float cn = fg * c[j] + ig * gg;
            float hn = og * tanhf(cn);
            out_nh[((size_t)t * BATCH + b0 + b) * 128 + u] = hn;
            if (t < TSTEPS - 1) {
                c[j] = cn * dm[j];
                s_h[b * 136 + u] = __float2half(hn * dm[j]);
            } else {
                out_h[(b0 + b) * 128 + u] = hn;
                out_c[(b0 + b) * 128 + u] = cn;
            }
        }
        __syncthreads();

        // copy xg(t+1) gmem->smem; latency hides under next step's mma
        if (t < TSTEPS - 1) {
            const uint4* src = (const uint4*)(g_xgH + ((size_t)(t + 1) * BATCH + b0) * 512);
            ((uint4*)s_x)[tid]       = src[tid];
            ((uint4*)s_x)[tid + 256] = src[tid + 256];
        }
    }
}

// ---------------- launcher ----------------
extern "C" void kernel_launch(void* const* d_in, const int* in_sizes, int n_in,
                              void* d_out, int out_size)
{
    const float* image    = (const float*)d_in[0];
    const float* location = (const float*)d_in[1];
    const float* message  = (const float*)d_in[2];
    const int*   done     = (const int*)  d_in[3];
    const float* h0       = (const float*)d_in[4];
    const float* c0       = (const float*)d_in[5];
    const float* Wv1      = (const float*)d_in[6];
    const float* bv1      = (const float*)d_in[7];
    const float* Wv2      = (const float*)d_in[8];
    const float* bv2      = (const float*)d_in[9];
    const float* Wv3      = (const float*)d_in[10];
    const float* bv3      = (const float*)d_in[11];
    const float* Wv4      = (const float*)d_in[12];
    const float* bv4      = (const float*)d_in[13];
    const float* Wl       = (const float*)d_in[14];
    const float* bl       = (const float*)d_in[15];
    const float* Wm       = (const float*)d_in[16];
    const float* bm       = (const float*)d_in[17];
    const float* Wih      = (const float*)d_in[18];
    const float* bih      = (const float*)d_in[19];
    const float* Whh      = (const float*)d_in[20];
    const float* bhh      = (const float*)d_in[21];

    float* out_nh = (float*)d_out;
    float* out_h  = out_nh + (size_t)TB * 128;
    float* out_c  = out_h + (size_t)BATCH * 128;

    void *imgH, *f1H, *f2H, *f3H, *hidH, *xgH, *W1H, *W2H, *W3H, *W4H, *WihH, *bg;
    cudaGetSymbolAddress(&imgH, g_imgH);
    cudaGetSymbolAddress(&f1H,  g_f1H);
    cudaGetSymbolAddress(&f2H,  g_f2H);
    cudaGetSymbolAddress(&f3H,  g_f3H);
    cudaGetSymbolAddress(&hidH, g_hidH);
    cudaGetSymbolAddress(&xgH,  g_xgH);
    cudaGetSymbolAddress(&W1H,  g_W1H);
    cudaGetSymbolAddress(&W2H,  g_W2H);
    cudaGetSymbolAddress(&W3H,  g_W3H);
    cudaGetSymbolAddress(&W4H,  g_W4H);
    cudaGetSymbolAddress(&WihH, g_WihH);
    cudaGetSymbolAddress(&bg,   g_bg);

    const int gsm = 2 * 36864;                       // 73728 B
    const int lsm = 139264 + 2176 + 16512 + 8192;    // 166144 B
    cudaFuncSetAttribute(gemm_wmma<true,  false>, cudaFuncAttributeMaxDynamicSharedMemorySize, gsm);
    cudaFuncSetAttribute(gemm_wmma<false, false>, cudaFuncAttributeMaxDynamicSharedMemorySize, gsm);
    cudaFuncSetAttribute(lstm_wmma, cudaFuncAttributeMaxDynamicSharedMemorySize, lsm);

    prep_weights<<<256, 256>>>(Wv1, Wv2, Wv3, Wv4, Wih, bih, bhh, Whh);
    prep_img<<<TB * 32 / 256, 256>>>(image);

    gemm_wmma<true,  false><<<dim3(1024, 2), 256, gsm>>>((const __half*)imgH, (const __half*)W1H, bv1, f1H,  32, 256, 256);
    gemm_wmma<true,  false><<<dim3(1024, 2), 256, gsm>>>((const __half*)f1H,  (const __half*)W2H, bv2, f2H, 256, 256, 256);
    gemm_wmma<true,  false><<<dim3(1024, 1), 256, gsm>>>((const __half*)f2H,  (const __half*)W3H, bv3, f3H, 256, 128, 128);
    gemm_wmma<true,  false><<<dim3(1024, 1), 256, gsm>>>((const __half*)f3H,  (const __half*)W4H, bv4, hidH, 128, 16, 32);
    locmsg_h<<<(TB + 255) / 256, 256>>>(location, message, done, Wl, bl, Wm, bm);
    gemm_wmma<false, false><<<dim3(1024, 4), 256, gsm>>>((const __half*)hidH, (const __half*)WihH, (const float*)bg, xgH, 32, 512, 512);

    lstm_wmma<<<BATCH / LSTM_LB, 256, lsm>>>(done, h0, c0, out_nh, out_h, out_c);
}

// round 15
// speedup vs baseline: 1.1549x; 1.0324x over previous
#include <cuda_runtime.h>
#include <cuda_fp16.h>
#include <mma.h>
#include <cstdint>

using namespace nvcuda;

#define TB      131072
#define TSTEPS  256
#define BATCH   512

// ---------------- device scratch ----------------
__device__ __align__(16) __half g_imgH[TB * 32];
__device__ __align__(16) __half g_f1H [TB * 256];
__device__ __align__(16) __half g_f2H [TB * 256];
__device__ __align__(16) __half g_f3H [TB * 128];
__device__ __align__(16) __half g_hidH[TB * 32];
__device__ __align__(16) __half g_xgH [TB * 512];     // fp16, gate-permuted cols (u*4+g)
__device__ __align__(16) __half g_W1H [256 * 32];
__device__ __align__(16) __half g_W2H [256 * 256];
__device__ __align__(16) __half g_W3H [128 * 256];
__device__ __align__(16) __half g_W4H [16 * 128];
__device__ __align__(16) __half g_WihH[512 * 32];     // gate-permuted rows
__device__ __align__(16) float  g_bg  [512];          // gate-permuted
__device__ __align__(16) __half g_whh [512 * 136];    // gate-permuted rows, ld=136

// ---------------- cp.async helpers ----------------
__device__ __forceinline__ void cp16(void* dst_smem, const void* src) {
    uint32_t d = (uint32_t)__cvta_generic_to_shared(dst_smem);
    asm volatile("cp.async.cg.shared.global [%0], [%1], 16;" :: "r"(d), "l"(src));
}
#define CP_COMMIT() asm volatile("cp.async.commit_group;" ::: "memory")
#define CP_WAIT(n)  asm volatile("cp.async.wait_group %0;" :: "n"(n) : "memory")

// ---------------- WMMA fp16 GEMM, cp.async double-buffered (measured R13) ----------------
template<bool RELU, bool OUTF32>
__global__ void __launch_bounds__(256, 2)
gemm_wmma(const __half* __restrict__ A, const __half* __restrict__ Bw,
          const float* __restrict__ bias, void* __restrict__ Cout,
          int K, int Nvalid, int ldc)
{
    extern __shared__ __align__(16) unsigned char sm[];
    float* s_c = (float*)sm;

    const int tid = threadIdx.x, w = tid >> 5;
    const int m0 = blockIdx.x * 128, n0 = blockIdx.y * 128;
    const int wm = (w & 3) * 32;
    const int wn = (w >> 2) * 64;
    const int ntiles = (K + 63) >> 6;

    wmma::fragment<wmma::accumulator, 16, 16, 16, float> acc[2][4];
    #pragma unroll
    for (int i = 0; i < 2; i++)
        #pragma unroll
        for (int j = 0; j < 4; j++) wmma::fill_fragment(acc[i][j], 0.f);

    auto load_tile = [&](int kt, int stage) {
        int k0 = kt * 64;
        int kw = K - k0; if (kw > 64) kw = 64;
        int cpr = kw >> 3;
        __half* sa = (__half*)(sm + stage * 36864);
        __half* sb = sa + 128 * 72;
        for (int i = tid; i < 128 * cpr; i += 256) {
            int r = i / cpr, c = (i - r * cpr) << 3;
            cp16(sa + r * 72 + c, A + (size_t)(m0 + r) * K + k0 + c);
        }
        for (int i = tid; i < 128 * cpr; i += 256) {
            int r = i / cpr, c = (i - r * cpr) << 3;
            int rr = n0 + r; if (rr >= Nvalid) rr = Nvalid - 1;
            cp16(sb + r * 72 + c, Bw + (size_t)rr * K + k0 + c);
        }
        CP_COMMIT();
    };

    load_tile(0, 0);
    for (int kt = 0; kt < ntiles; kt++) {
        if (kt + 1 < ntiles) { load_tile(kt + 1, (kt + 1) & 1); CP_WAIT(1); }
        else                 { CP_WAIT(0); }
        __syncthreads();

        __half* sa = (__half*)(sm + (kt & 1) * 36864);
        __half* sb = sa + 128 * 72;
        int kw = K - kt * 64; if (kw > 64) kw = 64;
        const int steps = kw >> 4;
        for (int s = 0; s < steps; s++) {
            const int kk = s * 16;
            wmma::fragment<wmma::matrix_a, 16, 16, 16, half, wmma::row_major> af[2];
            wmma::fragment<wmma::matrix_b, 16, 16, 16, half, wmma::col_major> bf[4];
            #pragma unroll
            for (int i = 0; i < 2; i++)
                wmma::load_matrix_sync(af[i], sa + (wm + i * 16) * 72 + kk, 72);
            #pragma unroll
            for (int j = 0; j < 4; j++)
                wmma::load_matrix_sync(bf[j], sb + (wn + j * 16) * 72 + kk, 72);
            #pragma unroll
            for (int i = 0; i < 2; i++)
                #pragma unroll
                for (int j = 0; j < 4; j++)
                    wmma::mma_sync(acc[i][j], af[i], bf[j], acc[i][j]);
        }
        __syncthreads();
    }

    #pragma unroll
    for (int i = 0; i < 2; i++)
        #pragma unroll
        for (int j = 0; j < 4; j++)
            wmma::store_matrix_sync(s_c + (wm + i * 16) * 132 + wn + j * 16,
                                    acc[i][j], 132, wmma::mem_row_major);
    __syncthreads();

    const int r  = tid >> 1;
    const int ch = (tid & 1) << 6;
    const int row = m0 + r;
    int ncols = Nvalid - n0; if (ncols > 128) ncols = 128;

    if (OUTF32) {
        float* cp = (float*)Cout + (size_t)row * ldc + n0;
        #pragma unroll
        for (int q = 0; q < 16; q++) {
            int c0 = ch + q * 4;
            if (c0 >= ncols) break;
            float4 v;
            v.x = s_c[r * 132 + c0 + 0] + __ldg(bias + n0 + c0 + 0);
            v.y = s_c[r * 132 + c0 + 1] + __ldg(bias + n0 + c0 + 1);
            v.z = s_c[r * 132 + c0 + 2] + __ldg(bias + n0 + c0 + 2);
            v.w = s_c[r * 132 + c0 + 3] + __ldg(bias + n0 + c0 + 3);
            if (RELU) {
                v.x = fmaxf(v.x, 0.f); v.y = fmaxf(v.y, 0.f);
                v.z = fmaxf(v.z, 0.f); v.w = fmaxf(v.w, 0.f);
            }
            *(float4*)(cp + c0) = v;
        }
    } else {
        __half* cp = (__half*)Cout + (size_t)row * ldc + n0;
        #pragma unroll
        for (int q = 0; q < 8; q++) {
            int c0 = ch + q * 8;
            if (c0 >= ncols) break;
            __half2 hh[4];
            #pragma unroll
            for (int e = 0; e < 4; e++) {
                float x0 = s_c[r * 132 + c0 + 2 * e]     + __ldg(bias + n0 + c0 + 2 * e);
                float x1 = s_c[r * 132 + c0 + 2 * e + 1] + __ldg(bias + n0 + c0 + 2 * e + 1);
                if (RELU) { x0 = fmaxf(x0, 0.f); x1 = fmaxf(x1, 0.f); }
                hh[e] = __floats2half2_rn(x0, x1);
            }
            *(uint4*)(cp + c0) = *(uint4*)hh;
        }
    }
}

// ---------------- prep kernels (gate permutation: new row u*4+g <- old row g*128+u) ----------------
__global__ void prep_weights(const float* __restrict__ Wv1, const float* __restrict__ Wv2,
                             const float* __restrict__ Wv3, const float* __restrict__ Wv4,
                             const float* __restrict__ Wih, const float* __restrict__ bih,
                             const float* __restrict__ bhh, const float* __restrict__ Whh)
{
    int i = blockIdx.x * blockDim.x + threadIdx.x;
    if (i < 65536) {
        int nr = i >> 7, k = i & 127;
        int u = nr >> 2, g = nr & 3;
        g_whh[nr * 136 + k] = __float2half(Whh[((g << 7) + u) * 128 + k]);
        g_W2H[i] = __float2half(Wv2[i]);
    }
    if (i < 32768) g_W3H[i] = __float2half(Wv3[i]);
    if (i < 2048)  g_W4H[i] = __float2half(Wv4[i]);
    if (i < 8192) {
        int r = i >> 5, c = i & 31;
        g_W1H[i] = (c < 25) ? __float2half(Wv1[r * 25 + c]) : __half(0.f);
    }
    if (i < 16384) {
        int nr = i >> 5, c = i & 31;
        int u = nr >> 2, g = nr & 3;
        g_WihH[i] = (c < 24) ? __float2half(Wih[((g << 7) + u) * 24 + c]) : __half(0.f);
    }
    if (i < 512) {
        int u = i >> 2, g = i & 3;
        int orow = (g << 7) + u;
        g_bg[i] = bih[orow] + bhh[orow];
    }
}

__global__ void prep_img(const float* __restrict__ image)
{
    int i = blockIdx.x * blockDim.x + threadIdx.x;
    int r = i >> 5, c = i & 31;
    g_imgH[i] = (c < 25) ? __float2half(image[r * 25 + c] * (1.0f / 255.0f)) : __half(0.f);
}

__global__ void locmsg_h(const float* __restrict__ loc, const float* __restrict__ msg,
                         const int* __restrict__ done,
                         const float* __restrict__ Wl, const float* __restrict__ bl,
                         const float* __restrict__ Wm, const float* __restrict__ bm)
{
    int i = blockIdx.x * blockDim.x + threadIdx.x;
    if (i >= TB) return;
    float lx = loc[2 * i] * 0.1f, ly = loc[2 * i + 1] * 0.1f;
    float m = (1.f - (float)done[i]) * msg[i];
    __half h[16];
    #pragma unroll
    for (int c = 0; c < 4; c++) h[c] = __float2half(Wl[2*c] * lx + Wl[2*c+1] * ly + bl[c]);
    #pragma unroll
    for (int c = 0; c < 4; c++) h[4 + c] = __float2half(fmaxf(Wm[c] * m + bm[c], 0.f));
    #pragma unroll
    for (int c = 8; c < 16; c++) h[c] = __half(0.f);
    uint4* dst = (uint4*)(g_hidH + (size_t)i * 32 + 16);
    dst[0] = *(uint4*)&h[0];
    dst[1] = *(uint4*)&h[8];
}

// ---------------- tensor-core LSTM v3: 512 thr, warp-local gates, 1 barrier/step ----------------
__device__ __forceinline__ float sigf(float x) { return 1.f / (1.f + __expf(-x)); }

#define LSTM_LB 8
// smem offsets (bytes)
#define LSO_W   0
#define LSO_H   139264                 // 2 buffers x 8*136 halves (2176 B each)
#define LSO_G   (139264 + 4352)        // 16 warps x 8x36 f32 = 18432 B
#define LSO_X   (139264 + 4352 + 18432) // 2 buffers x 8*512 halves (8192 B each)
#define LSO_TOT (139264 + 4352 + 18432 + 16384)   // 178432 B

__global__ void __launch_bounds__(512, 1)
lstm_wmma(const int*   __restrict__ done,
          const float* __restrict__ h0,
          const float* __restrict__ c0,
          float* __restrict__ out_nh,
          float* __restrict__ out_h,
          float* __restrict__ out_c)
{
    extern __shared__ __align__(16) unsigned char sraw[];
    __half* s_w = (__half*)(sraw + LSO_W);
    __half* s_hb[2] = { (__half*)(sraw + LSO_H), (__half*)(sraw + LSO_H + 2176) };
    float*  s_g = (float*)(sraw + LSO_G);
    __half* s_xb[2] = { (__half*)(sraw + LSO_X), (__half*)(sraw + LSO_X + 8192) };

    const int tid  = threadIdx.x;
    const int w    = tid >> 5, lane = tid & 31;
    const int b0   = blockIdx.x * LSTM_LB;
    const int n0   = w * 32;                 // warp's 32 gate cols = units [8w,8w+8) x 4 gates
    const int ul   = w * 8 + (lane & 7);     // this thread's unit
    const int bp   = lane >> 3;              // batch base: cells (bp, bp+4)

    // stage Whh: 512*136 halves = 8704 uint4
    for (int i = tid; i < 8704; i += 512)
        ((uint4*)s_w)[i] = ((const uint4*)g_whh)[i];
    // h0 masked -> buffer 0
    for (int i = tid; i < LSTM_LB * 128; i += 512) {
        int b = i >> 7, uu = i & 127;
        float m = 1.f - (float)done[b0 + b];
        s_hb[0][b * 136 + uu] = __float2half(h0[(b0 + b) * 128 + uu] * m);
    }
    // xg(t=0) -> x buffer 0 : 8*512 halves = 512 uint4
    ((uint4*)s_xb[0])[tid] = ((const uint4*)(g_xgH + (size_t)b0 * 512))[tid];

    float c[2];
    #pragma unroll
    for (int j = 0; j < 2; j++) {
        int b = bp + j * 4;
        float m = 1.f - (float)done[b0 + b];
        c[j] = c0[(b0 + b) * 128 + ul] * m;
    }
    __syncthreads();

    // persistent Whh fragments: 8 k-steps x n32
    wmma::fragment<wmma::matrix_b, 8, 32, 16, half, wmma::col_major> bf[8];
    #pragma unroll
    for (int k = 0; k < 8; k++)
        wmma::load_matrix_sync(bf[k], s_w + n0 * 136 + k * 16, 136);

    wmma::fragment<wmma::accumulator, 8, 32, 16, float> acc;
    wmma::fragment<wmma::matrix_a, 8, 32, 16, half, wmma::row_major> af;
    float* gw = s_g + w * 288;               // warp-private 8x36

    for (int t = 0; t < TSTEPS; t++) {
        const int cur = t & 1, nxt = cur ^ 1;

        float dm[2];
        if (t < TSTEPS - 1) {
            #pragma unroll
            for (int j = 0; j < 2; j++)
                dm[j] = 1.f - (float)done[(t + 1) * BATCH + b0 + bp + j * 4];
        }

        wmma::fill_fragment(acc, 0.f);
        #pragma unroll
        for (int k = 0; k < 8; k++) {
            wmma::load_matrix_sync(af, s_hb[cur] + k * 16, 136);
            wmma::mma_sync(acc, af, bf[k], acc);
        }
        wmma::store_matrix_sync(gw, acc, 36, wmma::mem_row_major);
        __syncwarp();

        #pragma unroll
        for (int j = 0; j < 2; j++) {
            int b = bp + j * 4;
            const float* gp = gw + b * 36 + (lane & 7) * 4;
            uint2 xv = *(const uint2*)(s_xb[cur] + b * 512 + ul * 4);
            float2 xa = __half22float2(*(__half2*)&xv.x);
            float2 xb = __half22float2(*(__half2*)&xv.y);
            float ig = sigf (gp[0] + xa.x);
            float fg = sigf (gp[1] + xa.y);
            float gg = tanhf(gp[2] + xb.x);
            float og = sigf (gp[3] + xb.y);
            float cn = fg * c[j] + ig * gg;
            float hn = og * tanhf(cn);
            out_nh[((size_t)t * BATCH + b0 + b) * 128 + ul] = hn;
            if (t < TSTEPS - 1) {
                c[j] = cn * dm[j];
                s_hb[nxt][b * 136 + ul] = __float2half(hn * dm[j]);
            } else {
                out_h[(b0 + b) * 128 + ul] = hn;
                out_c[(b0 + b) * 128 + ul] = cn;
            }
        }

        // stage xg(t+1) into the other x buffer (read next interval, after barrier)
        if (t < TSTEPS - 1)
            ((uint4*)s_xb[nxt])[tid] =
                ((const uint4*)(g_xgH + ((size_t)(t + 1) * BATCH + b0) * 512))[tid];

        __syncthreads();
    }
}

// ---------------- launcher ----------------
extern "C" void kernel_launch(void* const* d_in, const int* in_sizes, int n_in,
                              void* d_out, int out_size)
{
    const float* image    = (const float*)d_in[0];
    const float* location = (const float*)d_in[1];
    const float* message  = (const float*)d_in[2];
    const int*   done     = (const int*)  d_in[3];
    const float* h0       = (const float*)d_in[4];
    const float* c0       = (const float*)d_in[5];
    const float* Wv1      = (const float*)d_in[6];
    const float* bv1      = (const float*)d_in[7];
    const float* Wv2      = (const float*)d_in[8];
    const float* bv2      = (const float*)d_in[9];
    const float* Wv3      = (const float*)d_in[10];
    const float* bv3      = (const float*)d_in[11];
    const float* Wv4      = (const float*)d_in[12];
    const float* bv4      = (const float*)d_in[13];
    const float* Wl       = (const float*)d_in[14];
    const float* bl       = (const float*)d_in[15];
    const float* Wm       = (const float*)d_in[16];
    const float* bm       = (const float*)d_in[17];
    const float* Wih      = (const float*)d_in[18];
    const float* bih      = (const float*)d_in[19];
    const float* Whh      = (const float*)d_in[20];
    const float* bhh      = (const float*)d_in[21];

    float* out_nh = (float*)d_out;
    float* out_h  = out_nh + (size_t)TB * 128;
    float* out_c  = out_h + (size_t)BATCH * 128;

    void *imgH, *f1H, *f2H, *f3H, *hidH, *xgH, *W1H, *W2H, *W3H, *W4H, *WihH, *bg;
    cudaGetSymbolAddress(&imgH, g_imgH);
    cudaGetSymbolAddress(&f1H,  g_f1H);
    cudaGetSymbolAddress(&f2H,  g_f2H);
    cudaGetSymbolAddress(&f3H,  g_f3H);
    cudaGetSymbolAddress(&hidH, g_hidH);
    cudaGetSymbolAddress(&xgH,  g_xgH);
    cudaGetSymbolAddress(&W1H,  g_W1H);
    cudaGetSymbolAddress(&W2H,  g_W2H);
    cudaGetSymbolAddress(&W3H,  g_W3H);
    cudaGetSymbolAddress(&W4H,  g_W4H);
    cudaGetSymbolAddress(&WihH, g_WihH);
    cudaGetSymbolAddress(&bg,   g_bg);

    const int gsm = 2 * 36864;               // 73728 B
    cudaFuncSetAttribute(gemm_wmma<true,  false>, cudaFuncAttributeMaxDynamicSharedMemorySize, gsm);
    cudaFuncSetAttribute(gemm_wmma<false, false>, cudaFuncAttributeMaxDynamicSharedMemorySize, gsm);
    cudaFuncSetAttribute(lstm_wmma, cudaFuncAttributeMaxDynamicSharedMemorySize, LSO_TOT);

    prep_weights<<<256, 256>>>(Wv1, Wv2, Wv3, Wv4, Wih, bih, bhh, Whh);
    prep_img<<<TB * 32 / 256, 256>>>(image);

    gemm_wmma<true,  false><<<dim3(1024, 2), 256, gsm>>>((const __half*)imgH, (const __half*)W1H, bv1, f1H,  32, 256, 256);
    gemm_wmma<true,  false><<<dim3(1024, 2), 256, gsm>>>((const __half*)f1H,  (const __half*)W2H, bv2, f2H, 256, 256, 256);
    gemm_wmma<true,  false><<<dim3(1024, 1), 256, gsm>>>((const __half*)f2H,  (const __half*)W3H, bv3, f3H, 256, 128, 128);
    gemm_wmma<true,  false><<<dim3(1024, 1), 256, gsm>>>((const __half*)f3H,  (const __half*)W4H, bv4, hidH, 128, 16, 32);
    locmsg_h<<<(TB + 255) / 256, 256>>>(location, message, done, Wl, bl, Wm, bm);
    gemm_wmma<false, false><<<dim3(1024, 4), 256, gsm>>>((const __half*)hidH, (const __half*)WihH, (const float*)bg, xgH, 32, 512, 512);

    lstm_wmma<<<BATCH / LSTM_LB, 512, LSO_TOT>>>(done, h0, c0, out_nh, out_h, out_c);
}

// round 16
// speedup vs baseline: 1.4280x; 1.2365x over previous
#include <cuda_runtime.h>
#include <cuda_fp16.h>
#include <mma.h>
#include <cstdint>

using namespace nvcuda;

#define TB      131072
#define TSTEPS  256
#define BATCH   512

// ---------------- device scratch ----------------
__device__ __align__(16) __half g_imgH[TB * 32];
__device__ __align__(16) __half g_f1H [TB * 256];
__device__ __align__(16) __half g_f2H [TB * 256];
__device__ __align__(16) __half g_f3H [TB * 128];
__device__ __align__(16) __half g_hidH[TB * 32];
__device__ __align__(16) __half g_xgH [TB * 512];     // fp16, gate-permuted cols (u*4+g)
__device__ __align__(16) __half g_W1H [256 * 32];
__device__ __align__(16) __half g_W2H [256 * 256];
__device__ __align__(16) __half g_W3H [128 * 256];
__device__ __align__(16) __half g_W4H [16 * 128];
__device__ __align__(16) __half g_WihH[512 * 32];     // gate-permuted rows
__device__ __align__(16) float  g_bg  [512];          // gate-permuted
__device__ __align__(16) __half g_whh [512 * 136];    // gate-permuted rows, ld=136
__device__ int g_segs[TSTEPS * BATCH];                // packed: b | ts<<9 | te<<18
__device__ int g_nseg;
__device__ int g_fetch;

// ---------------- cp.async helpers ----------------
__device__ __forceinline__ void cp16(void* dst_smem, const void* src) {
    uint32_t d = (uint32_t)__cvta_generic_to_shared(dst_smem);
    asm volatile("cp.async.cg.shared.global [%0], [%1], 16;" :: "r"(d), "l"(src));
}
#define CP_COMMIT() asm volatile("cp.async.commit_group;" ::: "memory")
#define CP_WAIT(n)  asm volatile("cp.async.wait_group %0;" :: "n"(n) : "memory")

// ---------------- WMMA fp16 GEMM, cp.async double-buffered (measured R13/R15) ----------------
template<bool RELU, bool OUTF32>
__global__ void __launch_bounds__(256, 2)
gemm_wmma(const __half* __restrict__ A, const __half* __restrict__ Bw,
          const float* __restrict__ bias, void* __restrict__ Cout,
          int K, int Nvalid, int ldc)
{
    extern __shared__ __align__(16) unsigned char sm[];
    float* s_c = (float*)sm;

    const int tid = threadIdx.x, w = tid >> 5;
    const int m0 = blockIdx.x * 128, n0 = blockIdx.y * 128;
    const int wm = (w & 3) * 32;
    const int wn = (w >> 2) * 64;
    const int ntiles = (K + 63) >> 6;

    wmma::fragment<wmma::accumulator, 16, 16, 16, float> acc[2][4];
    #pragma unroll
    for (int i = 0; i < 2; i++)
        #pragma unroll
        for (int j = 0; j < 4; j++) wmma::fill_fragment(acc[i][j], 0.f);

    auto load_tile = [&](int kt, int stage) {
        int k0 = kt * 64;
        int kw = K - k0; if (kw > 64) kw = 64;
        int cpr = kw >> 3;
        __half* sa = (__half*)(sm + stage * 36864);
        __half* sb = sa + 128 * 72;
        for (int i = tid; i < 128 * cpr; i += 256) {
            int r = i / cpr, c = (i - r * cpr) << 3;
            cp16(sa + r * 72 + c, A + (size_t)(m0 + r) * K + k0 + c);
        }
        for (int i = tid; i < 128 * cpr; i += 256) {
            int r = i / cpr, c = (i - r * cpr) << 3;
            int rr = n0 + r; if (rr >= Nvalid) rr = Nvalid - 1;
            cp16(sb + r * 72 + c, Bw + (size_t)rr * K + k0 + c);
        }
        CP_COMMIT();
    };

    load_tile(0, 0);
    for (int kt = 0; kt < ntiles; kt++) {
        if (kt + 1 < ntiles) { load_tile(kt + 1, (kt + 1) & 1); CP_WAIT(1); }
        else                 { CP_WAIT(0); }
        __syncthreads();

        __half* sa = (__half*)(sm + (kt & 1) * 36864);
        __half* sb = sa + 128 * 72;
        int kw = K - kt * 64; if (kw > 64) kw = 64;
        const int steps = kw >> 4;
        for (int s = 0; s < steps; s++) {
            const int kk = s * 16;
            wmma::fragment<wmma::matrix_a, 16, 16, 16, half, wmma::row_major> af[2];
            wmma::fragment<wmma::matrix_b, 16, 16, 16, half, wmma::col_major> bf[4];
            #pragma unroll
            for (int i = 0; i < 2; i++)
                wmma::load_matrix_sync(af[i], sa + (wm + i * 16) * 72 + kk, 72);
            #pragma unroll
            for (int j = 0; j < 4; j++)
                wmma::load_matrix_sync(bf[j], sb + (wn + j * 16) * 72 + kk, 72);
            #pragma unroll
            for (int i = 0; i < 2; i++)
                #pragma unroll
                for (int j = 0; j < 4; j++)
                    wmma::mma_sync(acc[i][j], af[i], bf[j], acc[i][j]);
        }
        __syncthreads();
    }

    #pragma unroll
    for (int i = 0; i < 2; i++)
        #pragma unroll
        for (int j = 0; j < 4; j++)
            wmma::store_matrix_sync(s_c + (wm + i * 16) * 132 + wn + j * 16,
                                    acc[i][j], 132, wmma::mem_row_major);
    __syncthreads();

    const int r  = tid >> 1;
    const int ch = (tid & 1) << 6;
    const int row = m0 + r;
    int ncols = Nvalid - n0; if (ncols > 128) ncols = 128;

    if (OUTF32) {
        float* cp = (float*)Cout + (size_t)row * ldc + n0;
        #pragma unroll
        for (int q = 0; q < 16; q++) {
            int c0 = ch + q * 4;
            if (c0 >= ncols) break;
            float4 v;
            v.x = s_c[r * 132 + c0 + 0] + __ldg(bias + n0 + c0 + 0);
            v.y = s_c[r * 132 + c0 + 1] + __ldg(bias + n0 + c0 + 1);
            v.z = s_c[r * 132 + c0 + 2] + __ldg(bias + n0 + c0 + 2);
            v.w = s_c[r * 132 + c0 + 3] + __ldg(bias + n0 + c0 + 3);
            if (RELU) {
                v.x = fmaxf(v.x, 0.f); v.y = fmaxf(v.y, 0.f);
                v.z = fmaxf(v.z, 0.f); v.w = fmaxf(v.w, 0.f);
            }
            *(float4*)(cp + c0) = v;
        }
    } else {
        __half* cp = (__half*)Cout + (size_t)row * ldc + n0;
        #pragma unroll
        for (int q = 0; q < 8; q++) {
            int c0 = ch + q * 8;
            if (c0 >= ncols) break;
            __half2 hh[4];
            #pragma unroll
            for (int e = 0; e < 4; e++) {
                float x0 = s_c[r * 132 + c0 + 2 * e]     + __ldg(bias + n0 + c0 + 2 * e);
                float x1 = s_c[r * 132 + c0 + 2 * e + 1] + __ldg(bias + n0 + c0 + 2 * e + 1);
                if (RELU) { x0 = fmaxf(x0, 0.f); x1 = fmaxf(x1, 0.f); }
                hh[e] = __floats2half2_rn(x0, x1);
            }
            *(uint4*)(cp + c0) = *(uint4*)hh;
        }
    }
}

// ---------------- prep kernels (gate permutation: new row u*4+g <- old row g*128+u) ----------------
__global__ void prep_weights(const float* __restrict__ Wv1, const float* __restrict__ Wv2,
                             const float* __restrict__ Wv3, const float* __restrict__ Wv4,
                             const float* __restrict__ Wih, const float* __restrict__ bih,
                             const float* __restrict__ bhh, const float* __restrict__ Whh)
{
    int i = blockIdx.x * blockDim.x + threadIdx.x;
    if (i < 65536) {
        int nr = i >> 7, k = i & 127;
        int u = nr >> 2, g = nr & 3;
        g_whh[nr * 136 + k] = __float2half(Whh[((g << 7) + u) * 128 + k]);
        g_W2H[i] = __float2half(Wv2[i]);
    }
    if (i < 32768) g_W3H[i] = __float2half(Wv3[i]);
    if (i < 2048)  g_W4H[i] = __float2half(Wv4[i]);
    if (i < 8192) {
        int r = i >> 5, c = i & 31;
        g_W1H[i] = (c < 25) ? __float2half(Wv1[r * 25 + c]) : __half(0.f);
    }
    if (i < 16384) {
        int nr = i >> 5, c = i & 31;
        int u = nr >> 2, g = nr & 3;
        g_WihH[i] = (c < 24) ? __float2half(Wih[((g << 7) + u) * 24 + c]) : __half(0.f);
    }
    if (i < 512) {
        int u = i >> 2, g = i & 3;
        int orow = (g << 7) + u;
        g_bg[i] = bih[orow] + bhh[orow];
    }
}

__global__ void prep_img(const float* __restrict__ image)
{
    int i = blockIdx.x * blockDim.x + threadIdx.x;
    int r = i >> 5, c = i & 31;
    g_imgH[i] = (c < 25) ? __float2half(image[r * 25 + c] * (1.0f / 255.0f)) : __half(0.f);
}

__global__ void locmsg_h(const float* __restrict__ loc, const float* __restrict__ msg,
                         const int* __restrict__ done,
                         const float* __restrict__ Wl, const float* __restrict__ bl,
                         const float* __restrict__ Wm, const float* __restrict__ bm)
{
    int i = blockIdx.x * blockDim.x + threadIdx.x;
    if (i >= TB) return;
    float lx = loc[2 * i] * 0.1f, ly = loc[2 * i + 1] * 0.1f;
    float m = (1.f - (float)done[i]) * msg[i];
    __half h[16];
    #pragma unroll
    for (int c = 0; c < 4; c++) h[c] = __float2half(Wl[2*c] * lx + Wl[2*c+1] * ly + bl[c]);
    #pragma unroll
    for (int c = 0; c < 4; c++) h[4 + c] = __float2half(fmaxf(Wm[c] * m + bm[c], 0.f));
    #pragma unroll
    for (int c = 8; c < 16; c++) h[c] = __half(0.f);
    uint4* dst = (uint4*)(g_hidH + (size_t)i * 32 + 16);
    dst[0] = *(uint4*)&h[0];
    dst[1] = *(uint4*)&h[8];
}

// ---------------- segmentation: cut at every done=1; counting-sort by length desc ----------------
__global__ void seg_kernel(const int* __restrict__ done)
{
    __shared__ int cnt[257];
    __shared__ int off[257];
    const int b = threadIdx.x;          // 512 threads, 1 block
    for (int i = b; i < 257; i += 512) cnt[i] = 0;
    __syncthreads();

    int ts = 0;
    for (int t = 1; t <= TSTEPS; t++) {
        bool cut = (t == TSTEPS) || (done[t * BATCH + b] != 0);
        if (cut) { atomicAdd(&cnt[t - ts], 1); ts = t; }
    }
    __syncthreads();
    if (b == 0) {
        int acc = 0;
        for (int l = 256; l >= 1; l--) { off[l] = acc; acc += cnt[l]; }
        g_nseg = acc;
        g_fetch = 0;
    }
    __syncthreads();

    ts = 0;
    for (int t = 1; t <= TSTEPS; t++) {
        bool cut = (t == TSTEPS) || (done[t * BATCH + b] != 0);
        if (cut) {
            int slot = atomicAdd(&off[t - ts], 1);
            g_segs[slot] = b | (ts << 9) | (t << 18);
            ts = t;
        }
    }
}

// ---------------- segment-parallel tensor-core LSTM ----------------
__device__ __forceinline__ float sigf(float x) { return 1.f / (1.f + __expf(-x)); }

// smem offsets (bytes)
#define LSG_W   0
#define LSG_H   139264                       // 2 x (8*136 halves) = 4352 B
#define LSG_G   (139264 + 4352)              // 16 warps x 8x36 f32 = 18432 B
#define LSG_M   (139264 + 4352 + 18432)      // meta: s_base + s_seg[8] (pad 64 B)
#define LSG_TOT (139264 + 4352 + 18432 + 64)

__global__ void __launch_bounds__(512, 1)
lstm_seg(const int*   __restrict__ done,
         const float* __restrict__ h0,
         const float* __restrict__ c0,
         float* __restrict__ out_nh,
         float* __restrict__ out_h,
         float* __restrict__ out_c)
{
    extern __shared__ __align__(16) unsigned char sraw[];
    __half* s_w  = (__half*)(sraw + LSG_W);
    __half* s_hb[2] = { (__half*)(sraw + LSG_H), (__half*)(sraw + LSG_H + 2176) };
    float*  s_g  = (float*)(sraw + LSG_G);
    int*    s_mt = (int*)(sraw + LSG_M);     // [0]=base, [1..8]=seg of row 0..7

    const int tid  = threadIdx.x;
    const int w    = tid >> 5, lane = tid & 31;
    const int ulc  = lane & 7;               // unit-local 0..7
    const int ul   = w * 8 + ulc;            // global unit
    const int bp   = lane >> 3;              // 0..3; rows bp, bp+4
    const int n0   = w * 32;

    for (int i = tid; i < 8704; i += 512)
        ((uint4*)s_w)[i] = ((const uint4*)g_whh)[i];
    __syncthreads();

    wmma::fragment<wmma::matrix_b, 8, 32, 16, half, wmma::col_major> bf[8];
    #pragma unroll
    for (int k = 0; k < 8; k++)
        wmma::load_matrix_sync(bf[k], s_w + n0 * 136 + k * 16, 136);

    wmma::fragment<wmma::accumulator, 8, 32, 16, float> acc;
    wmma::fragment<wmma::matrix_a, 8, 32, 16, half, wmma::row_major> af;
    float* gw = s_g + w * 288;

    const int n_seg = g_nseg;

    while (true) {
        __syncthreads();                                  // prior wave fully done
        if (tid == 0) s_mt[0] = atomicAdd(&g_fetch, 8);
        __syncthreads();
        const int base = s_mt[0];
        if (base >= n_seg) break;
        if (tid < 8) {
            int idx = base + tid;
            s_mt[1 + tid] = (idx < n_seg) ? g_segs[idx] : 0;   // 0 -> len 0, inactive
        }
        __syncthreads();

        // decode my 2 rows; seed h (buffer 0) and c
        int sb[2], sts[2], ste[2];
        float c[2];
        #pragma unroll
        for (int j = 0; j < 2; j++) {
            int r  = bp + j * 4;
            int sg = s_mt[1 + r];
            sb[j]  = sg & 511;
            sts[j] = (sg >> 9) & 511;
            ste[j] = (sg >> 18) & 511;
            float hs = 0.f, cs = 0.f;
            if (sts[j] == 0 && ste[j] > 0) {
                float m = 1.f - (float)done[sb[j]];
                hs = h0[sb[j] * 128 + ul] * m;
                cs = c0[sb[j] * 128 + ul] * m;
            }
            c[j] = cs;
            s_hb[0][r * 136 + ul] = __float2half(hs);
        }
        int maxlen = 0;
        #pragma unroll
        for (int r = 0; r < 8; r++) {
            int sg = s_mt[1 + r];
            int L  = ((sg >> 18) & 511) - ((sg >> 9) & 511);
            maxlen = max(maxlen, L);
        }
        __syncthreads();                                  // seeds visible

        for (int ws = 0; ws < maxlen; ws++) {
            const int cur = ws & 1, nxt = cur ^ 1;

            // per-cell x-gate prefetch (hides under mma)
            uint2 xv[2];
            bool  act[2];
            int   tt[2];
            #pragma unroll
            for (int j = 0; j < 2; j++) {
                tt[j]  = sts[j] + ws;
                act[j] = tt[j] < ste[j];
                xv[j]  = act[j]
                    ? *(const uint2*)(g_xgH + ((size_t)tt[j] * BATCH + sb[j]) * 512 + ul * 4)
                    : make_uint2(0, 0);
            }

            wmma::fill_fragment(acc, 0.f);
            #pragma unroll
            for (int k = 0; k < 8; k++) {
                wmma::load_matrix_sync(af, s_hb[cur] + k * 16, 136);
                wmma::mma_sync(acc, af, bf[k], acc);
            }
            wmma::store_matrix_sync(gw, acc, 36, wmma::mem_row_major);
            __syncwarp();

            #pragma unroll
            for (int j = 0; j < 2; j++) {
                int r = bp + j * 4;
                const float* gp = gw + r * 36 + ulc * 4;
                float2 xa = __half22float2(*(__half2*)&xv[j].x);
                float2 xb = __half22float2(*(__half2*)&xv[j].y);
                float ig = sigf (gp[0] + xa.x);
                float fg = sigf (gp[1] + xa.y);
                float gg = tanhf(gp[2] + xb.x);
                float og = sigf (gp[3] + xb.y);
                float cn = fg * c[j] + ig * gg;
                float hn = og * tanhf(cn);
                c[j] = cn;
                s_hb[nxt][r * 136 + ul] = __float2half(hn);
                if (act[j]) {
                    out_nh[((size_t)tt[j] * BATCH + sb[j]) * 128 + ul] = hn;
                    if (tt[j] == ste[j] - 1 && ste[j] == TSTEPS) {
                        out_h[sb[j] * 128 + ul] = hn;
                        out_c[sb[j] * 128 + ul] = cn;
                    }
                }
            }
            __syncthreads();
        }
    }
}

// ---------------- launcher ----------------
extern "C" void kernel_launch(void* const* d_in, const int* in_sizes, int n_in,
                              void* d_out, int out_size)
{
    const float* image    = (const float*)d_in[0];
    const float* location = (const float*)d_in[1];
    const float* message  = (const float*)d_in[2];
    const int*   done     = (const int*)  d_in[3];
    const float* h0       = (const float*)d_in[4];
    const float* c0       = (const float*)d_in[5];
    const float* Wv1      = (const float*)d_in[6];
    const float* bv1      = (const float*)d_in[7];
    const float* Wv2      = (const float*)d_in[8];
    const float* bv2      = (const float*)d_in[9];
    const float* Wv3      = (const float*)d_in[10];
    const float* bv3      = (const float*)d_in[11];
    const float* Wv4      = (const float*)d_in[12];
    const float* bv4      = (const float*)d_in[13];
    const float* Wl       = (const float*)d_in[14];
    const float* bl       = (const float*)d_in[15];
    const float* Wm       = (const float*)d_in[16];
    const float* bm       = (const float*)d_in[17];
    const float* Wih      = (const float*)d_in[18];
    const float* bih      = (const float*)d_in[19];
    const float* Whh      = (const float*)d_in[20];
    const float* bhh      = (const float*)d_in[21];

    float* out_nh = (float*)d_out;
    float* out_h  = out_nh + (size_t)TB * 128;
    float* out_c  = out_h + (size_t)BATCH * 128;

    void *imgH, *f1H, *f2H, *f3H, *hidH, *xgH, *W1H, *W2H, *W3H, *W4H, *WihH, *bg;
    cudaGetSymbolAddress(&imgH, g_imgH);
    cudaGetSymbolAddress(&f1H,  g_f1H);
    cudaGetSymbolAddress(&f2H,  g_f2H);
    cudaGetSymbolAddress(&f3H,  g_f3H);
    cudaGetSymbolAddress(&hidH, g_hidH);
    cudaGetSymbolAddress(&xgH,  g_xgH);
    cudaGetSymbolAddress(&W1H,  g_W1H);
    cudaGetSymbolAddress(&W2H,  g_W2H);
    cudaGetSymbolAddress(&W3H,  g_W3H);
    cudaGetSymbolAddress(&W4H,  g_W4H);
    cudaGetSymbolAddress(&WihH, g_WihH);
    cudaGetSymbolAddress(&bg,   g_bg);

    const int gsm = 2 * 36864;               // 73728 B
    cudaFuncSetAttribute(gemm_wmma<true,  false>, cudaFuncAttributeMaxDynamicSharedMemorySize, gsm);
    cudaFuncSetAttribute(gemm_wmma<false, false>, cudaFuncAttributeMaxDynamicSharedMemorySize, gsm);
    cudaFuncSetAttribute(lstm_seg, cudaFuncAttributeMaxDynamicSharedMemorySize, LSG_TOT);

    prep_weights<<<256, 256>>>(Wv1, Wv2, Wv3, Wv4, Wih, bih, bhh, Whh);
    prep_img<<<TB * 32 / 256, 256>>>(image);
    seg_kernel<<<1, 512>>>(done);

    gemm_wmma<true,  false><<<dim3(1024, 2), 256, gsm>>>((const __half*)imgH, (const __half*)W1H, bv1, f1H,  32, 256, 256);
    gemm_wmma<true,  false><<<dim3(1024, 2), 256, gsm>>>((const __half*)f1H,  (const __half*)W2H, bv2, f2H, 256, 256, 256);
    gemm_wmma<true,  false><<<dim3(1024, 1), 256, gsm>>>((const __half*)f2H,  (const __half*)W3H, bv3, f3H, 256, 128, 128);
    gemm_wmma<true,  false><<<dim3(1024, 1), 256, gsm>>>((const __half*)f3H,  (const __half*)W4H, bv4, hidH, 128, 16, 32);
    locmsg_h<<<(TB + 255) / 256, 256>>>(location, message, done, Wl, bl, Wm, bm);
    gemm_wmma<false, false><<<dim3(1024, 4), 256, gsm>>>((const __half*)hidH, (const __half*)WihH, (const float*)bg, xgH, 32, 512, 512);

    lstm_seg<<<148, 512, LSG_TOT>>>(done, h0, c0, out_nh, out_h, out_c);
}

// round 17
// speedup vs baseline: 1.4939x; 1.0462x over previous
#include <cuda_runtime.h>
#include <cuda_fp16.h>
#include <mma.h>
#include <cstdint>

using namespace nvcuda;

#define TB      131072
#define TSTEPS  256
#define BATCH   512

// ---------------- device scratch ----------------
__device__ __align__(16) __half g_imgH[TB * 32];
__device__ __align__(16) __half g_f1H [TB * 256];
__device__ __align__(16) __half g_f2H [TB * 256];
__device__ __align__(16) __half g_f3H [TB * 128];
__device__ __align__(16) __half g_hidH[TB * 32];
__device__ __align__(16) __half g_xgH [TB * 512];     // fp16, gate-permuted cols (u*4+g)
__device__ __align__(16) __half g_W1H [256 * 32];
__device__ __align__(16) __half g_W2H [256 * 256];
__device__ __align__(16) __half g_W3H [128 * 256];
__device__ __align__(16) __half g_W4H [16 * 128];
__device__ __align__(16) __half g_WihH[512 * 32];     // gate-permuted rows
__device__ __align__(16) float  g_bg  [512];          // gate-permuted
__device__ __align__(16) __half g_whh [512 * 136];    // gate-permuted rows, ld=136
__device__ int g_segs[TSTEPS * BATCH];                // packed: b | ts<<9 | te<<18
__device__ int g_nseg;
__device__ int g_fetch;

// ---------------- cp.async helpers ----------------
__device__ __forceinline__ void cp16(void* dst_smem, const void* src) {
    uint32_t d = (uint32_t)__cvta_generic_to_shared(dst_smem);
    asm volatile("cp.async.cg.shared.global [%0], [%1], 16;" :: "r"(d), "l"(src));
}
#define CP_COMMIT() asm volatile("cp.async.commit_group;" ::: "memory")
#define CP_WAIT(n)  asm volatile("cp.async.wait_group %0;" :: "n"(n) : "memory")

// ---------------- WMMA fp16 GEMM, cp.async double-buffered, smem-cached bias ----------------
template<bool RELU, bool OUTF32>
__global__ void __launch_bounds__(256, 2)
gemm_wmma(const __half* __restrict__ A, const __half* __restrict__ Bw,
          const float* __restrict__ bias, void* __restrict__ Cout,
          int K, int Nvalid, int ldc)
{
    extern __shared__ __align__(16) unsigned char sm[];
    float* s_c    = (float*)sm;                  // overlays both tile stages
    float* s_bias = (float*)(sm + 73728);        // 128 f32, persistent

    const int tid = threadIdx.x, w = tid >> 5;
    const int m0 = blockIdx.x * 128, n0 = blockIdx.y * 128;
    const int wm = (w & 3) * 32;
    const int wn = (w >> 2) * 64;
    const int ntiles = (K + 63) >> 6;

    // cache bias once (before any barrier; epilogue reads after barriers)
    if (tid < 128)
        s_bias[tid] = (n0 + tid < Nvalid) ? bias[n0 + tid] : 0.f;

    wmma::fragment<wmma::accumulator, 16, 16, 16, float> acc[2][4];
    #pragma unroll
    for (int i = 0; i < 2; i++)
        #pragma unroll
        for (int j = 0; j < 4; j++) wmma::fill_fragment(acc[i][j], 0.f);

    auto load_tile = [&](int kt, int stage) {
        int k0 = kt * 64;
        int kw = K - k0; if (kw > 64) kw = 64;
        int cpr = kw >> 3;
        __half* sa = (__half*)(sm + stage * 36864);
        __half* sb = sa + 128 * 72;
        for (int i = tid; i < 128 * cpr; i += 256) {
            int r = i / cpr, c = (i - r * cpr) << 3;
            cp16(sa + r * 72 + c, A + (size_t)(m0 + r) * K + k0 + c);
        }
        for (int i = tid; i < 128 * cpr; i += 256) {
            int r = i / cpr, c = (i - r * cpr) << 3;
            int rr = n0 + r; if (rr >= Nvalid) rr = Nvalid - 1;
            cp16(sb + r * 72 + c, Bw + (size_t)rr * K + k0 + c);
        }
        CP_COMMIT();
    };

    load_tile(0, 0);
    for (int kt = 0; kt < ntiles; kt++) {
        if (kt + 1 < ntiles) { load_tile(kt + 1, (kt + 1) & 1); CP_WAIT(1); }
        else                 { CP_WAIT(0); }
        __syncthreads();

        __half* sa = (__half*)(sm + (kt & 1) * 36864);
        __half* sb = sa + 128 * 72;
        int kw = K - kt * 64; if (kw > 64) kw = 64;
        const int steps = kw >> 4;
        for (int s = 0; s < steps; s++) {
            const int kk = s * 16;
            wmma::fragment<wmma::matrix_a, 16, 16, 16, half, wmma::row_major> af[2];
            wmma::fragment<wmma::matrix_b, 16, 16, 16, half, wmma::col_major> bf[4];
            #pragma unroll
            for (int i = 0; i < 2; i++)
                wmma::load_matrix_sync(af[i], sa + (wm + i * 16) * 72 + kk, 72);
            #pragma unroll
            for (int j = 0; j < 4; j++)
                wmma::load_matrix_sync(bf[j], sb + (wn + j * 16) * 72 + kk, 72);
            #pragma unroll
            for (int i = 0; i < 2; i++)
                #pragma unroll
                for (int j = 0; j < 4; j++)
                    wmma::mma_sync(acc[i][j], af[i], bf[j], acc[i][j]);
        }
        __syncthreads();
    }

    #pragma unroll
    for (int i = 0; i < 2; i++)
        #pragma unroll
        for (int j = 0; j < 4; j++)
            wmma::store_matrix_sync(s_c + (wm + i * 16) * 132 + wn + j * 16,
                                    acc[i][j], 132, wmma::mem_row_major);
    __syncthreads();

    const int r  = tid >> 1;
    const int ch = (tid & 1) << 6;
    const int row = m0 + r;
    int ncols = Nvalid - n0; if (ncols > 128) ncols = 128;

    if (OUTF32) {
        float* cp = (float*)Cout + (size_t)row * ldc + n0;
        #pragma unroll
        for (int q = 0; q < 16; q++) {
            int c0 = ch + q * 4;
            if (c0 >= ncols) break;
            float4 v;
            v.x = s_c[r * 132 + c0 + 0] + s_bias[c0 + 0];
            v.y = s_c[r * 132 + c0 + 1] + s_bias[c0 + 1];
            v.z = s_c[r * 132 + c0 + 2] + s_bias[c0 + 2];
            v.w = s_c[r * 132 + c0 + 3] + s_bias[c0 + 3];
            if (RELU) {
                v.x = fmaxf(v.x, 0.f); v.y = fmaxf(v.y, 0.f);
                v.z = fmaxf(v.z, 0.f); v.w = fmaxf(v.w, 0.f);
            }
            *(float4*)(cp + c0) = v;
        }
    } else {
        __half* cp = (__half*)Cout + (size_t)row * ldc + n0;
        #pragma unroll
        for (int q = 0; q < 8; q++) {
            int c0 = ch + q * 8;
            if (c0 >= ncols) break;
            __half2 hh[4];
            #pragma unroll
            for (int e = 0; e < 4; e++) {
                float x0 = s_c[r * 132 + c0 + 2 * e]     + s_bias[c0 + 2 * e];
                float x1 = s_c[r * 132 + c0 + 2 * e + 1] + s_bias[c0 + 2 * e + 1];
                if (RELU) { x0 = fmaxf(x0, 0.f); x1 = fmaxf(x1, 0.f); }
                hh[e] = __floats2half2_rn(x0, x1);
            }
            *(uint4*)(cp + c0) = *(uint4*)hh;
        }
    }
}

// ---------------- prep kernels (gate permutation: new row u*4+g <- old row g*128+u) ----------------
__global__ void prep_weights(const float* __restrict__ Wv1, const float* __restrict__ Wv2,
                             const float* __restrict__ Wv3, const float* __restrict__ Wv4,
                             const float* __restrict__ Wih, const float* __restrict__ bih,
                             const float* __restrict__ bhh, const float* __restrict__ Whh)
{
    int i = blockIdx.x * blockDim.x + threadIdx.x;
    if (i < 65536) {
        int nr = i >> 7, k = i & 127;
        int u = nr >> 2, g = nr & 3;
        g_whh[nr * 136 + k] = __float2half(Whh[((g << 7) + u) * 128 + k]);
        g_W2H[i] = __float2half(Wv2[i]);
    }
    if (i < 32768) g_W3H[i] = __float2half(Wv3[i]);
    if (i < 2048)  g_W4H[i] = __float2half(Wv4[i]);
    if (i < 8192) {
        int r = i >> 5, c = i & 31;
        g_W1H[i] = (c < 25) ? __float2half(Wv1[r * 25 + c]) : __half(0.f);
    }
    if (i < 16384) {
        int nr = i >> 5, c = i & 31;
        int u = nr >> 2, g = nr & 3;
        g_WihH[i] = (c < 24) ? __float2half(Wih[((g << 7) + u) * 24 + c]) : __half(0.f);
    }
    if (i < 512) {
        int u = i >> 2, g = i & 3;
        int orow = (g << 7) + u;
        g_bg[i] = bih[orow] + bhh[orow];
    }
}

__global__ void prep_img(const float* __restrict__ image)
{
    int i = blockIdx.x * blockDim.x + threadIdx.x;
    int r = i >> 5, c = i & 31;
    g_imgH[i] = (c < 25) ? __float2half(image[r * 25 + c] * (1.0f / 255.0f)) : __half(0.f);
}

__global__ void locmsg_h(const float* __restrict__ loc, const float* __restrict__ msg,
                         const int* __restrict__ done,
                         const float* __restrict__ Wl, const float* __restrict__ bl,
                         const float* __restrict__ Wm, const float* __restrict__ bm)
{
    int i = blockIdx.x * blockDim.x + threadIdx.x;
    if (i >= TB) return;
    float lx = loc[2 * i] * 0.1f, ly = loc[2 * i + 1] * 0.1f;
    float m = (1.f - (float)done[i]) * msg[i];
    __half h[16];
    #pragma unroll
    for (int c = 0; c < 4; c++) h[c] = __float2half(Wl[2*c] * lx + Wl[2*c+1] * ly + bl[c]);
    #pragma unroll
    for (int c = 0; c < 4; c++) h[4 + c] = __float2half(fmaxf(Wm[c] * m + bm[c], 0.f));
    #pragma unroll
    for (int c = 8; c < 16; c++) h[c] = __half(0.f);
    uint4* dst = (uint4*)(g_hidH + (size_t)i * 32 + 16);
    dst[0] = *(uint4*)&h[0];
    dst[1] = *(uint4*)&h[8];
}

// ---------------- segmentation: cut at every done=1; counting-sort by length desc ----------------
__global__ void seg_kernel(const int* __restrict__ done)
{
    __shared__ int cnt[257];
    __shared__ int off[257];
    const int b = threadIdx.x;          // 512 threads, 1 block
    for (int i = b; i < 257; i += 512) cnt[i] = 0;
    __syncthreads();

    int ts = 0;
    for (int t = 1; t <= TSTEPS; t++) {
        bool cut = (t == TSTEPS) || (done[t * BATCH + b] != 0);
        if (cut) { atomicAdd(&cnt[t - ts], 1); ts = t; }
    }
    __syncthreads();
    if (b == 0) {
        int acc = 0;
        for (int l = 256; l >= 1; l--) { off[l] = acc; acc += cnt[l]; }
        g_nseg = acc;
        g_fetch = 0;
    }
    __syncthreads();

    ts = 0;
    for (int t = 1; t <= TSTEPS; t++) {
        bool cut = (t == TSTEPS) || (done[t * BATCH + b] != 0);
        if (cut) {
            int slot = atomicAdd(&off[t - ts], 1);
            g_segs[slot] = b | (ts << 9) | (t << 18);
            ts = t;
        }
    }
}

// ---------------- segment-parallel tensor-core LSTM (measured R16) ----------------
__device__ __forceinline__ float sigf(float x) { return 1.f / (1.f + __expf(-x)); }

// smem offsets (bytes)
#define LSG_W   0
#define LSG_H   139264
#define LSG_G   (139264 + 4352)
#define LSG_M   (139264 + 4352 + 18432)
#define LSG_TOT (139264 + 4352 + 18432 + 64)

__global__ void __launch_bounds__(512, 1)
lstm_seg(const int*   __restrict__ done,
         const float* __restrict__ h0,
         const float* __restrict__ c0,
         float* __restrict__ out_nh,
         float* __restrict__ out_h,
         float* __restrict__ out_c)
{
    extern __shared__ __align__(16) unsigned char sraw[];
    __half* s_w  = (__half*)(sraw + LSG_W);
    __half* s_hb[2] = { (__half*)(sraw + LSG_H), (__half*)(sraw + LSG_H + 2176) };
    float*  s_g  = (float*)(sraw + LSG_G);
    int*    s_mt = (int*)(sraw + LSG_M);

    const int tid  = threadIdx.x;
    const int w    = tid >> 5, lane = tid & 31;
    const int ulc  = lane & 7;
    const int ul   = w * 8 + ulc;
    const int bp   = lane >> 3;
    const int n0   = w * 32;

    for (int i = tid; i < 8704; i += 512)
        ((uint4*)s_w)[i] = ((const uint4*)g_whh)[i];
    __syncthreads();

    wmma::fragment<wmma::matrix_b, 8, 32, 16, half, wmma::col_major> bf[8];
    #pragma unroll
    for (int k = 0; k < 8; k++)
        wmma::load_matrix_sync(bf[k], s_w + n0 * 136 + k * 16, 136);

    wmma::fragment<wmma::accumulator, 8, 32, 16, float> acc;
    wmma::fragment<wmma::matrix_a, 8, 32, 16, half, wmma::row_major> af;
    float* gw = s_g + w * 288;

    const int n_seg = g_nseg;

    while (true) {
        __syncthreads();
        if (tid == 0) s_mt[0] = atomicAdd(&g_fetch, 8);
        __syncthreads();
        const int base = s_mt[0];
        if (base >= n_seg) break;
        if (tid < 8) {
            int idx = base + tid;
            s_mt[1 + tid] = (idx < n_seg) ? g_segs[idx] : 0;
        }
        __syncthreads();

        int sb[2], sts[2], ste[2];
        float c[2];
        #pragma unroll
        for (int j = 0; j < 2; j++) {
            int r  = bp + j * 4;
            int sg = s_mt[1 + r];
            sb[j]  = sg & 511;
            sts[j] = (sg >> 9) & 511;
            ste[j] = (sg >> 18) & 511;
            float hs = 0.f, cs = 0.f;
            if (sts[j] == 0 && ste[j] > 0) {
                float m = 1.f - (float)done[sb[j]];
                hs = h0[sb[j] * 128 + ul] * m;
                cs = c0[sb[j] * 128 + ul] * m;
            }
            c[j] = cs;
            s_hb[0][r * 136 + ul] = __float2half(hs);
        }
        int maxlen = 0;
        #pragma unroll
        for (int r = 0; r < 8; r++) {
            int sg = s_mt[1 + r];
            int L  = ((sg >> 18) & 511) - ((sg >> 9) & 511);
            maxlen = max(maxlen, L);
        }
        __syncthreads();

        for (int ws = 0; ws < maxlen; ws++) {
            const int cur = ws & 1, nxt = cur ^ 1;

            uint2 xv[2];
            bool  act[2];
            int   tt[2];
            #pragma unroll
            for (int j = 0; j < 2; j++) {
                tt[j]  = sts[j] + ws;
                act[j] = tt[j] < ste[j];
                xv[j]  = act[j]
                    ? *(const uint2*)(g_xgH + ((size_t)tt[j] * BATCH + sb[j]) * 512 + ul * 4)
                    : make_uint2(0, 0);
            }

            wmma::fill_fragment(acc, 0.f);
            #pragma unroll
            for (int k = 0; k < 8; k++) {
                wmma::load_matrix_sync(af, s_hb[cur] + k * 16, 136);
                wmma::mma_sync(acc, af, bf[k], acc);
            }
            wmma::store_matrix_sync(gw, acc, 36, wmma::mem_row_major);
            __syncwarp();

            #pragma unroll
            for (int j = 0; j < 2; j++) {
                int r = bp + j * 4;
                const float* gp = gw + r * 36 + ulc * 4;
                float2 xa = __half22float2(*(__half2*)&xv[j].x);
                float2 xb = __half22float2(*(__half2*)&xv[j].y);
                float ig = sigf (gp[0] + xa.x);
                float fg = sigf (gp[1] + xa.y);
                float gg = tanhf(gp[2] + xb.x);
                float og = sigf (gp[3] + xb.y);
                float cn = fg * c[j] + ig * gg;
                float hn = og * tanhf(cn);
                c[j] = cn;
                s_hb[nxt][r * 136 + ul] = __float2half(hn);
                if (act[j]) {
                    out_nh[((size_t)tt[j] * BATCH + sb[j]) * 128 + ul] = hn;
                    if (tt[j] == ste[j] - 1 && ste[j] == TSTEPS) {
                        out_h[sb[j] * 128 + ul] = hn;
                        out_c[sb[j] * 128 + ul] = cn;
                    }
                }
            }
            __syncthreads();
        }
    }
}

// ---------------- launcher ----------------
extern "C" void kernel_launch(void* const* d_in, const int* in_sizes, int n_in,
                              void* d_out, int out_size)
{
    const float* image    = (const float*)d_in[0];
    const float* location = (const float*)d_in[1];
    const float* message  = (const float*)d_in[2];
    const int*   done     = (const int*)  d_in[3];
    const float* h0       = (const float*)d_in[4];
    const float* c0       = (const float*)d_in[5];
    const float* Wv1      = (const float*)d_in[6];
    const float* bv1      = (const float*)d_in[7];
    const float* Wv2      = (const float*)d_in[8];
    const float* bv2      = (const float*)d_in[9];
    const float* Wv3      = (const float*)d_in[10];
    const float* bv3      = (const float*)d_in[11];
    const float* Wv4      = (const float*)d_in[12];
    const float* bv4      = (const float*)d_in[13];
    const float* Wl       = (const float*)d_in[14];
    const float* bl       = (const float*)d_in[15];
    const float* Wm       = (const float*)d_in[16];
    const float* bm       = (const float*)d_in[17];
    const float* Wih      = (const float*)d_in[18];
    const float* bih      = (const float*)d_in[19];
    const float* Whh      = (const float*)d_in[20];
    const float* bhh      = (const float*)d_in[21];

    float* out_nh = (float*)d_out;
    float* out_h  = out_nh + (size_t)TB * 128;
    float* out_c  = out_h + (size_t)BATCH * 128;

    void *imgH, *f1H, *f2H, *f3H, *hidH, *xgH, *W1H, *W2H, *W3H, *W4H, *WihH, *bg;
    cudaGetSymbolAddress(&imgH, g_imgH);
    cudaGetSymbolAddress(&f1H,  g_f1H);
    cudaGetSymbolAddress(&f2H,  g_f2H);
    cudaGetSymbolAddress(&f3H,  g_f3H);
    cudaGetSymbolAddress(&hidH, g_hidH);
    cudaGetSymbolAddress(&xgH,  g_xgH);
    cudaGetSymbolAddress(&W1H,  g_W1H);
    cudaGetSymbolAddress(&W2H,  g_W2H);
    cudaGetSymbolAddress(&W3H,  g_W3H);
    cudaGetSymbolAddress(&W4H,  g_W4H);
    cudaGetSymbolAddress(&WihH, g_WihH);
    cudaGetSymbolAddress(&bg,   g_bg);

    const int gsm = 2 * 36864 + 512;         // 74240 B (tiles/s_c + s_bias)
    cudaFuncSetAttribute(gemm_wmma<true,  false>, cudaFuncAttributeMaxDynamicSharedMemorySize, gsm);
    cudaFuncSetAttribute(gemm_wmma<false, false>, cudaFuncAttributeMaxDynamicSharedMemorySize, gsm);
    cudaFuncSetAttribute(lstm_seg, cudaFuncAttributeMaxDynamicSharedMemorySize, LSG_TOT);

    prep_weights<<<256, 256>>>(Wv1, Wv2, Wv3, Wv4, Wih, bih, bhh, Whh);
    prep_img<<<TB * 32 / 256, 256>>>(image);
    seg_kernel<<<1, 512>>>(done);

    gemm_wmma<true,  false><<<dim3(1024, 2), 256, gsm>>>((const __half*)imgH, (const __half*)W1H, bv1, f1H,  32, 256, 256);
    gemm_wmma<true,  false><<<dim3(1024, 2), 256, gsm>>>((const __half*)f1H,  (const __half*)W2H, bv2, f2H, 256, 256, 256);
    gemm_wmma<true,  false><<<dim3(1024, 1), 256, gsm>>>((const __half*)f2H,  (const __half*)W3H, bv3, f3H, 256, 128, 128);
    gemm_wmma<true,  false><<<dim3(1024, 1), 256, gsm>>>((const __half*)f3H,  (const __half*)W4H, bv4, hidH, 128, 16, 32);
    locmsg_h<<<(TB + 255) / 256, 256>>>(location, message, done, Wl, bl, Wm, bm);
    gemm_wmma<false, false><<<dim3(1024, 4), 256, gsm>>>((const __half*)hidH, (const __half*)WihH, (const float*)bg, xgH, 32, 512, 512);

    lstm_seg<<<148, 512, LSG_TOT>>>(done, h0, c0, out_nh, out_h, out_c);
}